// round 3
// baseline (speedup 1.0000x reference)
#include <cuda_runtime.h>
#include <cuda_bf16.h>
#include <cstdint>

#define T_STEPS 500
#define BATCH   512
#define CIN     128
#define NHID    512
#define NB      128          // persistent blocks; 4 neurons each
#define NT      512          // threads per block; 1 batch row each

// ---------------- static device scratch (no allocations allowed) ----------------
__device__ float g_xtr[(size_t)T_STEPS * BATCH * CIN];        // [(t*B+b)][c]
__device__ float g_in1[(size_t)T_STEPS * BATCH * NHID];       // x@W1^T + b1 + br2
__device__ float g_W1T[CIN * NHID];                           // [c][n]
// time-indexed spike byte-masks: g_m1[t+1][row][g] = nibble of s1[t] for neurons 4g..4g+3
__device__ unsigned char g_m1[T_STEPS + 1][BATCH][NB];
__device__ unsigned char g_m2[T_STEPS + 1][BATCH][NB];
__device__ unsigned g_ctr;                                    // grid barrier counter

// ---------------- init: reset barrier counter only ------------------------------
__global__ void k_init() { g_ctr = 0u; }

// ---------------- x[b][c][t] -> g_xtr[(t*B+b)][c] -------------------------------
__global__ void k_transpose_x(const float* __restrict__ x) {
    __shared__ float tile[32][33];
    int b = blockIdx.z;
    int t0 = blockIdx.x * 32, c0 = blockIdx.y * 32;
    int tx = threadIdx.x, ty = threadIdx.y;
#pragma unroll
    for (int i = 0; i < 32; i += 8) {
        int c = c0 + ty + i, t = t0 + tx;
        if (t < T_STEPS && c < CIN)
            tile[ty + i][tx] = x[((size_t)b * CIN + c) * T_STEPS + t];
    }
    __syncthreads();
#pragma unroll
    for (int i = 0; i < 32; i += 8) {
        int t = t0 + ty + i, c = c0 + tx;
        if (t < T_STEPS && c < CIN)
            g_xtr[((size_t)t * BATCH + b) * CIN + c] = tile[tx][ty + i];
    }
}

// ---------------- W1[n][c] -> g_W1T[c][n] ----------------------------------------
__global__ void k_transpose_w1(const float* __restrict__ W1) {
    __shared__ float tile[32][33];
    int c0 = blockIdx.x * 32, n0 = blockIdx.y * 32;
    int tx = threadIdx.x, ty = threadIdx.y;
#pragma unroll
    for (int i = 0; i < 32; i += 8) {
        int n = n0 + ty + i, c = c0 + tx;
        if (n < NHID && c < CIN) tile[ty + i][tx] = W1[(size_t)n * CIN + c];
    }
    __syncthreads();
#pragma unroll
    for (int i = 0; i < 32; i += 8) {
        int c = c0 + ty + i, n = n0 + tx;
        if (n < NHID && c < CIN) g_W1T[(size_t)c * NHID + n] = tile[tx][ty + i];
    }
}

// ---------------- in1 = xtr @ W1T + (b1 + br2); M=256000, K=128, N=512 -----------
__global__ __launch_bounds__(256)
void k_gemm_in1(const float* __restrict__ b1, const float* __restrict__ br2) {
    __shared__ float As[32][129];
    __shared__ float Bs[32][64];
    const float* A = g_xtr;
    const float* B = g_W1T;
    int bm = blockIdx.x * 128, bn = blockIdx.y * 64;
    int tid = threadIdx.x;
    int tx = tid & 15, ty = tid >> 4;
    int arow = tid >> 3, acol = (tid & 7) * 4;
    int brow = tid >> 4, bcol = (tid & 15) * 4;

    float acc[8][4];
#pragma unroll
    for (int i = 0; i < 8; i++)
#pragma unroll
        for (int j = 0; j < 4; j++) acc[i][j] = 0.0f;

    for (int k0 = 0; k0 < CIN; k0 += 32) {
#pragma unroll
        for (int i = 0; i < 4; i++) {
            float4 v = *(const float4*)(A + (size_t)(bm + arow + 32 * i) * CIN + k0 + acol);
            As[acol + 0][arow + 32 * i] = v.x;
            As[acol + 1][arow + 32 * i] = v.y;
            As[acol + 2][arow + 32 * i] = v.z;
            As[acol + 3][arow + 32 * i] = v.w;
        }
#pragma unroll
        for (int i = 0; i < 2; i++) {
            *(float4*)&Bs[brow + 16 * i][bcol] =
                *(const float4*)(B + (size_t)(k0 + brow + 16 * i) * NHID + bn + bcol);
        }
        __syncthreads();
#pragma unroll
        for (int k = 0; k < 32; k++) {
            float a[8];
#pragma unroll
            for (int i = 0; i < 8; i++) a[i] = As[k][ty * 8 + i];
            float4 bv = *(const float4*)&Bs[k][tx * 4];
#pragma unroll
            for (int i = 0; i < 8; i++) {
                acc[i][0] += a[i] * bv.x;
                acc[i][1] += a[i] * bv.y;
                acc[i][2] += a[i] * bv.z;
                acc[i][3] += a[i] * bv.w;
            }
        }
        __syncthreads();
    }
    int col = bn + tx * 4;
    float bb0 = b1[col + 0] + br2[col + 0];
    float bb1 = b1[col + 1] + br2[col + 1];
    float bb2 = b1[col + 2] + br2[col + 2];
    float bb3 = b1[col + 3] + br2[col + 3];
#pragma unroll
    for (int i = 0; i < 8; i++) {
        size_t row = (size_t)(bm + ty * 8 + i);
        float4 o;
        o.x = acc[i][0] + bb0;
        o.y = acc[i][1] + bb1;
        o.z = acc[i][2] + bb2;
        o.w = acc[i][3] + bb3;
        *(float4*)(g_in1 + row * NHID + bn + tx * 4) = o;
    }
}

// ---------------- mask walk helpers (ascending j order, single accumulators) -----
// byte-lane mask word: 4 bytes = blocks 4wi..4wi+3, low nibble of each byte used.
__device__ __forceinline__ void walk2(unsigned m, int base,
                                      const float4* __restrict__ A,
                                      const float4* __restrict__ B,
                                      float4& a1, float4& a2) {
    while (m) {
        int b = __ffs(m) - 1;
        m &= m - 1u;
        int j = base + ((b >> 3) << 2) + (b & 7);
        float4 wa = A[j];
        float4 wb = B[j];
        a1.x += wa.x; a1.y += wa.y; a1.z += wa.z; a1.w += wa.w;
        a2.x += wb.x; a2.y += wb.y; a2.z += wb.z; a2.w += wb.w;
    }
}

__device__ __forceinline__ void walk1(unsigned m, int base,
                                      const float4* __restrict__ A, float4& a1) {
    while (m) {
        int b = __ffs(m) - 1;
        m &= m - 1u;
        int j = base + ((b >> 3) << 2) + (b & 7);
        float4 wa = A[j];
        a1.x += wa.x; a1.y += wa.y; a1.z += wa.z; a1.w += wa.w;
    }
}

__device__ __forceinline__ void walkro(unsigned m, int base,
                                       const float2* __restrict__ W, float& ax, float& ay) {
    while (m) {
        int b = __ffs(m) - 1;
        m &= m - 1u;
        int j = base + ((b >> 3) << 2) + (b & 7);
        float2 wv = W[j];
        ax += wv.x;
        ay += wv.y;
    }
}

// ---------------- persistent recurrent kernel ------------------------------------
__global__ __launch_bounds__(NT, 1)
void k_rsnn(const float* __restrict__ Wr2, const float* __restrict__ W2,
            const float* __restrict__ W4,
            const float* __restrict__ b2, const float* __restrict__ br2,
            const float* __restrict__ b4,
            const float* __restrict__ Vth1, const float* __restrict__ tau1,
            const float* __restrict__ Vth2, const float* __restrict__ tau2,
            const float* __restrict__ tau_out,
            float* __restrict__ out) {
    __shared__ float4 WAsh[NHID];   // [j] -> Wr2[n0..n0+3][j]
    __shared__ float4 WBsh[NHID];   // [j] -> W2 [n0..n0+3][j]
    __shared__ float2 W4sh[NHID];   // [j] -> W4[0][j], W4[1][j]

    const int tid = threadIdx.x;    // owns batch row `tid`
    const int g = blockIdx.x;
    const int n0 = g * 4;

    WAsh[tid] = make_float4(Wr2[(size_t)(n0 + 0) * NHID + tid], Wr2[(size_t)(n0 + 1) * NHID + tid],
                            Wr2[(size_t)(n0 + 2) * NHID + tid], Wr2[(size_t)(n0 + 3) * NHID + tid]);
    WBsh[tid] = make_float4(W2[(size_t)(n0 + 0) * NHID + tid], W2[(size_t)(n0 + 1) * NHID + tid],
                            W2[(size_t)(n0 + 2) * NHID + tid], W2[(size_t)(n0 + 3) * NHID + tid]);
    W4sh[tid] = make_float2(W4[tid], W4[NHID + tid]);
    __syncthreads();

    const float4 t1v = *(const float4*)(tau1 + n0);
    const float4 v1v = *(const float4*)(Vth1 + n0);
    const float4 t2v = *(const float4*)(tau2 + n0);
    const float4 v2v = *(const float4*)(Vth2 + n0);
    float4 bias2;
    bias2.x = b2[n0 + 0] + br2[n0 + 0];
    bias2.y = b2[n0 + 1] + br2[n0 + 1];
    bias2.z = b2[n0 + 2] + br2[n0 + 2];
    bias2.w = b2[n0 + 3] + br2[n0 + 3];

    const float4 z4 = make_float4(0.f, 0.f, 0.f, 0.f);
    float4 mem1 = z4, sp1 = z4, cnt1 = z4;
    float4 mem2 = z4, sp2 = z4, cnt2 = z4;

    // readout: threads 0..3 own rows n0+tid
    float memo_x = 0.f, memo_y = 0.f;
    const int rowR = n0 + tid;
    const float to0 = tau_out[0], to1 = tau_out[1];
    const float b40 = b4[0], b41 = b4[1];

    for (int p = 0; p < T_STEPS + 2; p++) {
        // ---- gather over s1[p-1] mask (feeds layer1-rec and layer2-ff) ----
        float4 a1 = z4, a2 = z4;
        if (p <= T_STEPS) {
            const uint4* mp = (const uint4*)&g_m1[p][tid][0];
            uint4 q[8];
#pragma unroll
            for (int c = 0; c < 8; c++) q[c] = __ldcg(mp + c);
#pragma unroll
            for (int c = 0; c < 8; c++) {
                walk2(q[c].x, c * 64 +  0, WAsh, WBsh, a1, a2);
                walk2(q[c].y, c * 64 + 16, WAsh, WBsh, a1, a2);
                walk2(q[c].z, c * 64 + 32, WAsh, WBsh, a1, a2);
                walk2(q[c].w, c * 64 + 48, WAsh, WBsh, a1, a2);
            }
        }

        // ---- layer 1, t = p ----
        if (p < T_STEPS) {
            float4 i1 = *(const float4*)(g_in1 + ((size_t)p * BATCH + tid) * NHID + n0);
            i1.x += a1.x; i1.y += a1.y; i1.z += a1.z; i1.w += a1.w;
            mem1.x = t1v.x * mem1.x * (1.f - sp1.x) + i1.x;
            mem1.y = t1v.y * mem1.y * (1.f - sp1.y) + i1.y;
            mem1.z = t1v.z * mem1.z * (1.f - sp1.z) + i1.z;
            mem1.w = t1v.w * mem1.w * (1.f - sp1.w) + i1.w;
            float sx = (mem1.x > v1v.x) ? 1.f : 0.f;
            float sy = (mem1.y > v1v.y) ? 1.f : 0.f;
            float sz = (mem1.z > v1v.z) ? 1.f : 0.f;
            float sw = (mem1.w > v1v.w) ? 1.f : 0.f;
            sp1 = make_float4(sx, sy, sz, sw);
            cnt1.x += sx; cnt1.y += sy; cnt1.z += sz; cnt1.w += sw;
            unsigned nib = (sx > 0.f ? 1u : 0u) | (sy > 0.f ? 2u : 0u) |
                           (sz > 0.f ? 4u : 0u) | (sw > 0.f ? 8u : 0u);
            g_m1[p + 1][tid][g] = (unsigned char)nib;
        }

        // ---- layer 2, t = p-1 ----
        if (p >= 1 && p <= T_STEPS) {
            float4 r2 = z4;
            const uint4* mp = (const uint4*)&g_m2[p - 1][tid][0];
            uint4 q[8];
#pragma unroll
            for (int c = 0; c < 8; c++) q[c] = __ldcg(mp + c);
#pragma unroll
            for (int c = 0; c < 8; c++) {
                walk1(q[c].x, c * 64 +  0, WAsh, r2);
                walk1(q[c].y, c * 64 + 16, WAsh, r2);
                walk1(q[c].z, c * 64 + 32, WAsh, r2);
                walk1(q[c].w, c * 64 + 48, WAsh, r2);
            }
            float4 i2;
            i2.x = a2.x + r2.x + bias2.x;
            i2.y = a2.y + r2.y + bias2.y;
            i2.z = a2.z + r2.z + bias2.z;
            i2.w = a2.w + r2.w + bias2.w;
            mem2.x = t2v.x * mem2.x * (1.f - sp2.x) + i2.x;
            mem2.y = t2v.y * mem2.y * (1.f - sp2.y) + i2.y;
            mem2.z = t2v.z * mem2.z * (1.f - sp2.z) + i2.z;
            mem2.w = t2v.w * mem2.w * (1.f - sp2.w) + i2.w;
            float sx = (mem2.x > v2v.x) ? 1.f : 0.f;
            float sy = (mem2.y > v2v.y) ? 1.f : 0.f;
            float sz = (mem2.z > v2v.z) ? 1.f : 0.f;
            float sw = (mem2.w > v2v.w) ? 1.f : 0.f;
            sp2 = make_float4(sx, sy, sz, sw);
            cnt2.x += sx; cnt2.y += sy; cnt2.z += sz; cnt2.w += sw;
            unsigned nib = (sx > 0.f ? 1u : 0u) | (sy > 0.f ? 2u : 0u) |
                           (sz > 0.f ? 4u : 0u) | (sw > 0.f ? 8u : 0u);
            g_m2[p][tid][g] = (unsigned char)nib;
        }

        // ---- readout for t = p-2 (reads s2[p-2] = g_m2[p-1]) ----
        if (p >= 2 && tid < 4) {
            const uint4* mp = (const uint4*)&g_m2[p - 1][rowR][0];
            uint4 q[8];
#pragma unroll
            for (int c = 0; c < 8; c++) q[c] = __ldcg(mp + c);
            float ax = 0.f, ay = 0.f;
#pragma unroll
            for (int c = 0; c < 8; c++) {
                walkro(q[c].x, c * 64 +  0, W4sh, ax, ay);
                walkro(q[c].y, c * 64 + 16, W4sh, ax, ay);
                walkro(q[c].z, c * 64 + 32, W4sh, ax, ay);
                walkro(q[c].w, c * 64 + 48, W4sh, ax, ay);
            }
            memo_x = to0 * memo_x + ax + b40;
            memo_y = to1 * memo_y + ay + b41;
            int t = p - 2;
            out[(size_t)rowR * (2 * T_STEPS) + t] = memo_x;
            out[(size_t)rowR * (2 * T_STEPS) + T_STEPS + t] = memo_y;
        }

        // ---- grid barrier: release arrive + acquire poll (no L1-flushing fence) ----
        __syncthreads();
        if (tid == 0) {
            asm volatile("red.release.gpu.global.add.u32 [%0], %1;"
                         :: "l"(&g_ctr), "r"(1u) : "memory");
            unsigned target = (unsigned)(p + 1) * (unsigned)NB;
            unsigned v;
            for (;;) {
                asm volatile("ld.acquire.gpu.global.u32 %0, [%1];"
                             : "=r"(v) : "l"(&g_ctr) : "memory");
                if ((int)(v - target) >= 0) break;
                __nanosleep(32);
            }
        }
        __syncthreads();
    }

    // ---- spike-count outputs: sc1 at offset B*2*T, sc2 after it ----
    const float inv = 1.f / (float)T_STEPS;
    float* sc1 = out + (size_t)BATCH * 2 * T_STEPS;
    float* sc2 = sc1 + (size_t)BATCH * NHID;
    *(float4*)(sc1 + (size_t)tid * NHID + n0) =
        make_float4(cnt1.x * inv, cnt1.y * inv, cnt1.z * inv, cnt1.w * inv);
    *(float4*)(sc2 + (size_t)tid * NHID + n0) =
        make_float4(cnt2.x * inv, cnt2.y * inv, cnt2.z * inv, cnt2.w * inv);
}

// ---------------- launch ----------------------------------------------------------
extern "C" void kernel_launch(void* const* d_in, const int* in_sizes, int n_in,
                              void* d_out, int out_size) {
    (void)in_sizes; (void)n_in; (void)out_size;
    const float* x    = (const float*)d_in[0];
    const float* W1   = (const float*)d_in[1];
    const float* b1   = (const float*)d_in[2];
    const float* W2   = (const float*)d_in[3];
    const float* b2   = (const float*)d_in[4];
    const float* Wr2  = (const float*)d_in[5];
    const float* br2  = (const float*)d_in[6];
    // d_in[7..10]: W3, b3, Wr3, br3 — dead (layer 3 never reaches outputs)
    const float* W4   = (const float*)d_in[11];
    const float* b4   = (const float*)d_in[12];
    const float* Vth1 = (const float*)d_in[13];
    const float* tau1 = (const float*)d_in[14];
    const float* Vth2 = (const float*)d_in[15];
    const float* tau2 = (const float*)d_in[16];
    // d_in[17..18]: Vth3, tau3 — dead
    const float* tau_out = (const float*)d_in[19];
    float* out = (float*)d_out;

    k_init<<<1, 1>>>();
    k_transpose_x<<<dim3((T_STEPS + 31) / 32, CIN / 32, BATCH), dim3(32, 8)>>>(x);
    k_transpose_w1<<<dim3(CIN / 32, NHID / 32), dim3(32, 8)>>>(W1);
    k_gemm_in1<<<dim3((T_STEPS * BATCH) / 128, NHID / 64), 256>>>(b1, br2);
    k_rsnn<<<NB, NT>>>(Wr2, W2, W4, b2, br2, b4,
                       Vth1, tau1, Vth2, tau2, tau_out, out);
}

// round 4
// speedup vs baseline: 1.3064x; 1.3064x over previous
#include <cuda_runtime.h>
#include <cuda_bf16.h>
#include <cstdint>

#define T_STEPS 500
#define BATCH   512
#define CIN     128
#define NHID    512
#define NBLK    128          // independent blocks; 4 batch rows each
#define RPB     4
#define NT      512          // 128 threads per row; thread owns 4 neurons

// ---------------- static device scratch (no allocations allowed) ----------------
__device__ float g_xtr[(size_t)T_STEPS * BATCH * CIN];    // [(t*B+b)][c]
__device__ float g_in1[(size_t)T_STEPS * BATCH * NHID];   // x@W1^T + b1 + br2
__device__ float g_W1T[CIN * NHID];                       // [c][n]
// packed gather tables: [j][q] -> {Wr2[4q..4q+3][j], W2[4q..4q+3][j]}
__device__ float4 g_Wpk[(size_t)NHID * 128 * 2];

// ---------------- x[b][c][t] -> g_xtr[(t*B+b)][c] -------------------------------
__global__ void k_transpose_x(const float* __restrict__ x) {
    __shared__ float tile[32][33];
    int b = blockIdx.z;
    int t0 = blockIdx.x * 32, c0 = blockIdx.y * 32;
    int tx = threadIdx.x, ty = threadIdx.y;
#pragma unroll
    for (int i = 0; i < 32; i += 8) {
        int c = c0 + ty + i, t = t0 + tx;
        if (t < T_STEPS && c < CIN)
            tile[ty + i][tx] = x[((size_t)b * CIN + c) * T_STEPS + t];
    }
    __syncthreads();
#pragma unroll
    for (int i = 0; i < 32; i += 8) {
        int t = t0 + ty + i, c = c0 + tx;
        if (t < T_STEPS && c < CIN)
            g_xtr[((size_t)t * BATCH + b) * CIN + c] = tile[tx][ty + i];
    }
}

// ---------------- W1[n][c] -> g_W1T[c][n] ----------------------------------------
__global__ void k_transpose_w1(const float* __restrict__ W1) {
    __shared__ float tile[32][33];
    int c0 = blockIdx.x * 32, n0 = blockIdx.y * 32;
    int tx = threadIdx.x, ty = threadIdx.y;
#pragma unroll
    for (int i = 0; i < 32; i += 8) {
        int n = n0 + ty + i, c = c0 + tx;
        if (n < NHID && c < CIN) tile[ty + i][tx] = W1[(size_t)n * CIN + c];
    }
    __syncthreads();
#pragma unroll
    for (int i = 0; i < 32; i += 8) {
        int c = c0 + ty + i, n = n0 + tx;
        if (n < NHID && c < CIN) g_W1T[(size_t)c * NHID + n] = tile[tx][ty + i];
    }
}

// ---------------- pack Wr2/W2 columns for the gather ------------------------------
__global__ void k_pack(const float* __restrict__ Wr2, const float* __restrict__ W2) {
    int i = blockIdx.x * 256 + threadIdx.x;        // 0 .. 512*128-1
    int j = i >> 7, q = i & 127, n0 = q * 4;
    float4 a, b;
    a.x = Wr2[(size_t)(n0 + 0) * NHID + j];
    a.y = Wr2[(size_t)(n0 + 1) * NHID + j];
    a.z = Wr2[(size_t)(n0 + 2) * NHID + j];
    a.w = Wr2[(size_t)(n0 + 3) * NHID + j];
    b.x = W2[(size_t)(n0 + 0) * NHID + j];
    b.y = W2[(size_t)(n0 + 1) * NHID + j];
    b.z = W2[(size_t)(n0 + 2) * NHID + j];
    b.w = W2[(size_t)(n0 + 3) * NHID + j];
    g_Wpk[(size_t)i * 2 + 0] = a;
    g_Wpk[(size_t)i * 2 + 1] = b;
}

// ---------------- in1 = xtr @ W1T + (b1 + br2); M=256000, K=128, N=512 -----------
__global__ __launch_bounds__(256)
void k_gemm_in1(const float* __restrict__ b1, const float* __restrict__ br2) {
    __shared__ float As[32][129];
    __shared__ float Bs[32][64];
    const float* A = g_xtr;
    const float* B = g_W1T;
    int bm = blockIdx.x * 128, bn = blockIdx.y * 64;
    int tid = threadIdx.x;
    int tx = tid & 15, ty = tid >> 4;
    int arow = tid >> 3, acol = (tid & 7) * 4;
    int brow = tid >> 4, bcol = (tid & 15) * 4;

    float acc[8][4];
#pragma unroll
    for (int i = 0; i < 8; i++)
#pragma unroll
        for (int j = 0; j < 4; j++) acc[i][j] = 0.0f;

    for (int k0 = 0; k0 < CIN; k0 += 32) {
#pragma unroll
        for (int i = 0; i < 4; i++) {
            float4 v = *(const float4*)(A + (size_t)(bm + arow + 32 * i) * CIN + k0 + acol);
            As[acol + 0][arow + 32 * i] = v.x;
            As[acol + 1][arow + 32 * i] = v.y;
            As[acol + 2][arow + 32 * i] = v.z;
            As[acol + 3][arow + 32 * i] = v.w;
        }
#pragma unroll
        for (int i = 0; i < 2; i++) {
            *(float4*)&Bs[brow + 16 * i][bcol] =
                *(const float4*)(B + (size_t)(k0 + brow + 16 * i) * NHID + bn + bcol);
        }
        __syncthreads();
#pragma unroll
        for (int k = 0; k < 32; k++) {
            float a[8];
#pragma unroll
            for (int i = 0; i < 8; i++) a[i] = As[k][ty * 8 + i];
            float4 bv = *(const float4*)&Bs[k][tx * 4];
#pragma unroll
            for (int i = 0; i < 8; i++) {
                acc[i][0] += a[i] * bv.x;
                acc[i][1] += a[i] * bv.y;
                acc[i][2] += a[i] * bv.z;
                acc[i][3] += a[i] * bv.w;
            }
        }
        __syncthreads();
    }
    int col = bn + tx * 4;
    float bb0 = b1[col + 0] + br2[col + 0];
    float bb1 = b1[col + 1] + br2[col + 1];
    float bb2 = b1[col + 2] + br2[col + 2];
    float bb3 = b1[col + 3] + br2[col + 3];
#pragma unroll
    for (int i = 0; i < 8; i++) {
        size_t row = (size_t)(bm + ty * 8 + i);
        float4 o;
        o.x = acc[i][0] + bb0;
        o.y = acc[i][1] + bb1;
        o.z = acc[i][2] + bb2;
        o.w = acc[i][3] + bb3;
        *(float4*)(g_in1 + row * NHID + bn + tx * 4) = o;
    }
}

// ---------------- persistent per-block recurrent kernel (no grid sync) -----------
__global__ __launch_bounds__(NT, 1)
void k_rsnn(const float* __restrict__ W4,
            const float* __restrict__ b2, const float* __restrict__ br2,
            const float* __restrict__ b4,
            const float* __restrict__ Vth1, const float* __restrict__ tau1,
            const float* __restrict__ Vth2, const float* __restrict__ tau2,
            const float* __restrict__ tau_out,
            float* __restrict__ out) {
    __shared__ float2 W4sh[NHID];            // [j] -> {W4[0][j], W4[1][j]}
    __shared__ unsigned sm1[2][RPB][16];     // s1 masks, double buffered
    __shared__ unsigned sm2[2][RPB][16];     // s2 masks, double buffered
    __shared__ float redx[2][RPB][4];        // readout partials [parity][row][warp]
    __shared__ float redy[2][RPB][4];

    const int tid = threadIdx.x;
    const int r = tid >> 7;                  // local row 0..3
    const int q = tid & 127;                 // neuron group 0..127
    const int n0 = q * 4;                    // global neurons n0..n0+3
    const int lane = tid & 31;
    const int wq = (q >> 5);                 // warp within row 0..3
    const int rowg = blockIdx.x * RPB + r;   // global batch row

    W4sh[tid] = make_float2(W4[tid], W4[NHID + tid]);
    if (tid < 2 * RPB * 16) {
        ((unsigned*)sm1)[tid] = 0u;
        ((unsigned*)sm2)[tid] = 0u;
    }
    __syncthreads();

    const float4 t1v = *(const float4*)(tau1 + n0);
    const float4 v1v = *(const float4*)(Vth1 + n0);
    const float4 t2v = *(const float4*)(tau2 + n0);
    const float4 v2v = *(const float4*)(Vth2 + n0);
    float4 bias2;
    bias2.x = b2[n0 + 0] + br2[n0 + 0];
    bias2.y = b2[n0 + 1] + br2[n0 + 1];
    bias2.z = b2[n0 + 2] + br2[n0 + 2];
    bias2.w = b2[n0 + 3] + br2[n0 + 3];

    const float4 z4 = make_float4(0.f, 0.f, 0.f, 0.f);
    float4 mem1 = z4, sp1 = z4, cnt1 = z4;
    float4 mem2 = z4, sp2 = z4, cnt2 = z4;
    unsigned nib2_prev = 0u;                 // s2[t] nibble from previous phase
    float memo_x = 0.f, memo_y = 0.f;        // used by q==0 threads only
    const float to0 = tau_out[0], to1 = tau_out[1];
    const float b40 = b4[0], b41 = b4[1];

    const float4* __restrict__ Wpk = g_Wpk;

    // phase p: layer1 t=p (p<T), layer2 t=p-1 (1<=p<=T), readout t=p-2 (p>=2)
    for (int p = 0; p <= T_STEPS + 1; p++) {
        const int rb1 = (p + 1) & 1;         // buf holding s1[p-1]
        const int rb2 = p & 1;               // buf holding s2[p-2]

        // prefetch in1 row early
        float4 i1v = z4;
        if (p < T_STEPS)
            i1v = __ldcg((const float4*)(g_in1 + ((size_t)p * BATCH + rowg) * NHID + n0));

        // ---- combined walk over s1[p-1]: a1 (Wr2T) and f2 (W2T) ----
        float4 a1 = z4, f2 = z4;
        if (p <= T_STEPS) {
            const unsigned* mw = sm1[rb1][r];
#pragma unroll 4
            for (int w = 0; w < 16; w++) {
                unsigned m = mw[w];
                while (m) {
                    int b = __ffs(m) - 1;
                    m &= m - 1u;
                    const float4* pp = Wpk + ((((size_t)(w * 32 + b) << 7) + q) << 1);
                    float4 wa = __ldg(pp);
                    float4 wb = __ldg(pp + 1);
                    a1.x += wa.x; a1.y += wa.y; a1.z += wa.z; a1.w += wa.w;
                    f2.x += wb.x; f2.y += wb.y; f2.z += wb.z; f2.w += wb.w;
                }
            }
        }

        // ---- layer 1, t = p ----
        if (p < T_STEPS) {
            float4 i1 = i1v;
            i1.x += a1.x; i1.y += a1.y; i1.z += a1.z; i1.w += a1.w;
            mem1.x = t1v.x * mem1.x * (1.f - sp1.x) + i1.x;
            mem1.y = t1v.y * mem1.y * (1.f - sp1.y) + i1.y;
            mem1.z = t1v.z * mem1.z * (1.f - sp1.z) + i1.z;
            mem1.w = t1v.w * mem1.w * (1.f - sp1.w) + i1.w;
            float sx = (mem1.x > v1v.x) ? 1.f : 0.f;
            float sy = (mem1.y > v1v.y) ? 1.f : 0.f;
            float sz = (mem1.z > v1v.z) ? 1.f : 0.f;
            float sw = (mem1.w > v1v.w) ? 1.f : 0.f;
            sp1 = make_float4(sx, sy, sz, sw);
            cnt1.x += sx; cnt1.y += sy; cnt1.z += sz; cnt1.w += sw;
            unsigned nib = (sx > 0.f ? 1u : 0u) | (sy > 0.f ? 2u : 0u) |
                           (sz > 0.f ? 4u : 0u) | (sw > 0.f ? 8u : 0u);
            unsigned v = nib << ((q & 7) * 4);
            v |= __shfl_xor_sync(0xffffffffu, v, 1);
            v |= __shfl_xor_sync(0xffffffffu, v, 2);
            v |= __shfl_xor_sync(0xffffffffu, v, 4);
            if ((q & 7) == 0) sm1[p & 1][r][q >> 3] = v;   // s1[p]
        }

        // ---- layer 2, t = p-1 ----
        unsigned nib2_new = 0u;
        if (p >= 1 && p <= T_STEPS) {
            float4 r2 = z4;
            const unsigned* mw = sm2[rb2][r];
#pragma unroll 4
            for (int w = 0; w < 16; w++) {
                unsigned m = mw[w];
                while (m) {
                    int b = __ffs(m) - 1;
                    m &= m - 1u;
                    const float4* pp = Wpk + ((((size_t)(w * 32 + b) << 7) + q) << 1);
                    float4 wa = __ldg(pp);
                    r2.x += wa.x; r2.y += wa.y; r2.z += wa.z; r2.w += wa.w;
                }
            }
            float4 i2;
            i2.x = f2.x + r2.x + bias2.x;
            i2.y = f2.y + r2.y + bias2.y;
            i2.z = f2.z + r2.z + bias2.z;
            i2.w = f2.w + r2.w + bias2.w;
            mem2.x = t2v.x * mem2.x * (1.f - sp2.x) + i2.x;
            mem2.y = t2v.y * mem2.y * (1.f - sp2.y) + i2.y;
            mem2.z = t2v.z * mem2.z * (1.f - sp2.z) + i2.z;
            mem2.w = t2v.w * mem2.w * (1.f - sp2.w) + i2.w;
            float sx = (mem2.x > v2v.x) ? 1.f : 0.f;
            float sy = (mem2.y > v2v.y) ? 1.f : 0.f;
            float sz = (mem2.z > v2v.z) ? 1.f : 0.f;
            float sw = (mem2.w > v2v.w) ? 1.f : 0.f;
            sp2 = make_float4(sx, sy, sz, sw);
            cnt2.x += sx; cnt2.y += sy; cnt2.z += sz; cnt2.w += sw;
            nib2_new = (sx > 0.f ? 1u : 0u) | (sy > 0.f ? 2u : 0u) |
                       (sz > 0.f ? 4u : 0u) | (sw > 0.f ? 8u : 0u);
            unsigned v = nib2_new << ((q & 7) * 4);
            v |= __shfl_xor_sync(0xffffffffu, v, 1);
            v |= __shfl_xor_sync(0xffffffffu, v, 2);
            v |= __shfl_xor_sync(0xffffffffu, v, 4);
            if ((q & 7) == 0) sm2[(p + 1) & 1][r][q >> 3] = v;  // s2[p-1]
        }

        // ---- readout partials for t = p-2 (uses nib2_prev = s2[p-2]) ----
        {
            float ax = 0.f, ay = 0.f;
            unsigned nb = nib2_prev;
            if (nb & 1u) { float2 t = W4sh[n0 + 0]; ax += t.x; ay += t.y; }
            if (nb & 2u) { float2 t = W4sh[n0 + 1]; ax += t.x; ay += t.y; }
            if (nb & 4u) { float2 t = W4sh[n0 + 2]; ax += t.x; ay += t.y; }
            if (nb & 8u) { float2 t = W4sh[n0 + 3]; ax += t.x; ay += t.y; }
#pragma unroll
            for (int off = 16; off > 0; off >>= 1) {
                ax += __shfl_down_sync(0xffffffffu, ax, off);
                ay += __shfl_down_sync(0xffffffffu, ay, off);
            }
            if (lane == 0) {
                redx[p & 1][r][wq] = ax;
                redy[p & 1][r][wq] = ay;
            }
        }
        nib2_prev = nib2_new;

        __syncthreads();   // the ONLY sync per phase

        // ---- finalize readout t = p-2 ----
        if (p >= 2 && q == 0) {
            int par = p & 1;
            float ax = ((redx[par][r][0] + redx[par][r][1]) +
                        (redx[par][r][2] + redx[par][r][3]));
            float ay = ((redy[par][r][0] + redy[par][r][1]) +
                        (redy[par][r][2] + redy[par][r][3]));
            memo_x = to0 * memo_x + ax + b40;
            memo_y = to1 * memo_y + ay + b41;
            int t = p - 2;
            out[(size_t)rowg * (2 * T_STEPS) + t] = memo_x;
            out[(size_t)rowg * (2 * T_STEPS) + T_STEPS + t] = memo_y;
        }
    }

    // ---- spike-count outputs ----
    const float inv = 1.f / (float)T_STEPS;
    float* sc1 = out + (size_t)BATCH * 2 * T_STEPS;
    float* sc2 = sc1 + (size_t)BATCH * NHID;
    *(float4*)(sc1 + (size_t)rowg * NHID + n0) =
        make_float4(cnt1.x * inv, cnt1.y * inv, cnt1.z * inv, cnt1.w * inv);
    *(float4*)(sc2 + (size_t)rowg * NHID + n0) =
        make_float4(cnt2.x * inv, cnt2.y * inv, cnt2.z * inv, cnt2.w * inv);
}

// ---------------- launch ----------------------------------------------------------
extern "C" void kernel_launch(void* const* d_in, const int* in_sizes, int n_in,
                              void* d_out, int out_size) {
    (void)in_sizes; (void)n_in; (void)out_size;
    const float* x    = (const float*)d_in[0];
    const float* W1   = (const float*)d_in[1];
    const float* b1   = (const float*)d_in[2];
    const float* W2   = (const float*)d_in[3];
    const float* b2   = (const float*)d_in[4];
    const float* Wr2  = (const float*)d_in[5];
    const float* br2  = (const float*)d_in[6];
    // d_in[7..10]: W3, b3, Wr3, br3 — dead (layer 3 never reaches outputs)
    const float* W4   = (const float*)d_in[11];
    const float* b4   = (const float*)d_in[12];
    const float* Vth1 = (const float*)d_in[13];
    const float* tau1 = (const float*)d_in[14];
    const float* Vth2 = (const float*)d_in[15];
    const float* tau2 = (const float*)d_in[16];
    // d_in[17..18]: Vth3, tau3 — dead
    const float* tau_out = (const float*)d_in[19];
    float* out = (float*)d_out;

    k_transpose_x<<<dim3((T_STEPS + 31) / 32, CIN / 32, BATCH), dim3(32, 8)>>>(x);
    k_transpose_w1<<<dim3(CIN / 32, NHID / 32), dim3(32, 8)>>>(W1);
    k_pack<<<(NHID * 128) / 256, 256>>>(Wr2, W2);
    k_gemm_in1<<<dim3((T_STEPS * BATCH) / 128, NHID / 64), 256>>>(b1, br2);
    k_rsnn<<<NBLK, NT>>>(W4, b2, br2, b4, Vth1, tau1, Vth2, tau2, tau_out, out);
}

// round 5
// speedup vs baseline: 2.8198x; 2.1585x over previous
#include <cuda_runtime.h>
#include <cuda_bf16.h>
#include <cstdint>

#define T_STEPS 500
#define BATCH   512
#define CIN     128
#define NHID    512
#define NBLK    128          // independent blocks; 4 batch rows each
#define RPB     4
#define NT      512          // 128 threads per row; thread owns 4 neurons

// ---------------- static device scratch (no allocations allowed) ----------------
__device__ float g_xtr[(size_t)T_STEPS * BATCH * CIN];    // [(t*B+b)][c]
__device__ float g_in1[(size_t)T_STEPS * BATCH * NHID];   // x@W1^T + b1 + br2
__device__ float g_W1T[CIN * NHID];                       // [c][n]
// split gather tables: g_Wa[j*128+q] = Wr2[4q..4q+3][j], g_Wb likewise for W2
__device__ float4 g_Wa[(size_t)NHID * 128];
__device__ float4 g_Wb[(size_t)NHID * 128];

// ---------------- x[b][c][t] -> g_xtr[(t*B+b)][c] -------------------------------
__global__ void k_transpose_x(const float* __restrict__ x) {
    __shared__ float tile[32][33];
    int b = blockIdx.z;
    int t0 = blockIdx.x * 32, c0 = blockIdx.y * 32;
    int tx = threadIdx.x, ty = threadIdx.y;
#pragma unroll
    for (int i = 0; i < 32; i += 8) {
        int c = c0 + ty + i, t = t0 + tx;
        if (t < T_STEPS && c < CIN)
            tile[ty + i][tx] = x[((size_t)b * CIN + c) * T_STEPS + t];
    }
    __syncthreads();
#pragma unroll
    for (int i = 0; i < 32; i += 8) {
        int t = t0 + ty + i, c = c0 + tx;
        if (t < T_STEPS && c < CIN)
            g_xtr[((size_t)t * BATCH + b) * CIN + c] = tile[tx][ty + i];
    }
}

// ---------------- W1[n][c] -> g_W1T[c][n] ----------------------------------------
__global__ void k_transpose_w1(const float* __restrict__ W1) {
    __shared__ float tile[32][33];
    int c0 = blockIdx.x * 32, n0 = blockIdx.y * 32;
    int tx = threadIdx.x, ty = threadIdx.y;
#pragma unroll
    for (int i = 0; i < 32; i += 8) {
        int n = n0 + ty + i, c = c0 + tx;
        if (n < NHID && c < CIN) tile[ty + i][tx] = W1[(size_t)n * CIN + c];
    }
    __syncthreads();
#pragma unroll
    for (int i = 0; i < 32; i += 8) {
        int c = c0 + ty + i, n = n0 + tx;
        if (n < NHID && c < CIN) g_W1T[(size_t)c * NHID + n] = tile[tx][ty + i];
    }
}

// ---------------- pack Wr2/W2 columns for the gather ------------------------------
__global__ void k_pack(const float* __restrict__ Wr2, const float* __restrict__ W2) {
    int i = blockIdx.x * 256 + threadIdx.x;        // 0 .. 512*128-1
    int j = i >> 7, q = i & 127, n0 = q * 4;
    float4 a, b;
    a.x = Wr2[(size_t)(n0 + 0) * NHID + j];
    a.y = Wr2[(size_t)(n0 + 1) * NHID + j];
    a.z = Wr2[(size_t)(n0 + 2) * NHID + j];
    a.w = Wr2[(size_t)(n0 + 3) * NHID + j];
    b.x = W2[(size_t)(n0 + 0) * NHID + j];
    b.y = W2[(size_t)(n0 + 1) * NHID + j];
    b.z = W2[(size_t)(n0 + 2) * NHID + j];
    b.w = W2[(size_t)(n0 + 3) * NHID + j];
    g_Wa[i] = a;
    g_Wb[i] = b;
}

// ---------------- in1 = xtr @ W1T + (b1 + br2); M=256000, K=128, N=512 -----------
__global__ __launch_bounds__(256)
void k_gemm_in1(const float* __restrict__ b1, const float* __restrict__ br2) {
    __shared__ float As[32][129];
    __shared__ float Bs[32][64];
    const float* A = g_xtr;
    const float* B = g_W1T;
    int bm = blockIdx.x * 128, bn = blockIdx.y * 64;
    int tid = threadIdx.x;
    int tx = tid & 15, ty = tid >> 4;
    int arow = tid >> 3, acol = (tid & 7) * 4;
    int brow = tid >> 4, bcol = (tid & 15) * 4;

    float acc[8][4];
#pragma unroll
    for (int i = 0; i < 8; i++)
#pragma unroll
        for (int j = 0; j < 4; j++) acc[i][j] = 0.0f;

    for (int k0 = 0; k0 < CIN; k0 += 32) {
#pragma unroll
        for (int i = 0; i < 4; i++) {
            float4 v = *(const float4*)(A + (size_t)(bm + arow + 32 * i) * CIN + k0 + acol);
            As[acol + 0][arow + 32 * i] = v.x;
            As[acol + 1][arow + 32 * i] = v.y;
            As[acol + 2][arow + 32 * i] = v.z;
            As[acol + 3][arow + 32 * i] = v.w;
        }
#pragma unroll
        for (int i = 0; i < 2; i++) {
            *(float4*)&Bs[brow + 16 * i][bcol] =
                *(const float4*)(B + (size_t)(k0 + brow + 16 * i) * NHID + bn + bcol);
        }
        __syncthreads();
#pragma unroll
        for (int k = 0; k < 32; k++) {
            float a[8];
#pragma unroll
            for (int i = 0; i < 8; i++) a[i] = As[k][ty * 8 + i];
            float4 bv = *(const float4*)&Bs[k][tx * 4];
#pragma unroll
            for (int i = 0; i < 8; i++) {
                acc[i][0] += a[i] * bv.x;
                acc[i][1] += a[i] * bv.y;
                acc[i][2] += a[i] * bv.z;
                acc[i][3] += a[i] * bv.w;
            }
        }
        __syncthreads();
    }
    int col = bn + tx * 4;
    float bb0 = b1[col + 0] + br2[col + 0];
    float bb1 = b1[col + 1] + br2[col + 1];
    float bb2 = b1[col + 2] + br2[col + 2];
    float bb3 = b1[col + 3] + br2[col + 3];
#pragma unroll
    for (int i = 0; i < 8; i++) {
        size_t row = (size_t)(bm + ty * 8 + i);
        float4 o;
        o.x = acc[i][0] + bb0;
        o.y = acc[i][1] + bb1;
        o.z = acc[i][2] + bb2;
        o.w = acc[i][3] + bb3;
        *(float4*)(g_in1 + row * NHID + bn + tx * 4) = o;
    }
}

// ---------------- persistent per-block recurrent kernel (no grid sync) -----------
__global__ __launch_bounds__(NT, 1)
void k_rsnn(const float* __restrict__ W4,
            const float* __restrict__ b2, const float* __restrict__ br2,
            const float* __restrict__ b4,
            const float* __restrict__ Vth1, const float* __restrict__ tau1,
            const float* __restrict__ Vth2, const float* __restrict__ tau2,
            const float* __restrict__ tau_out,
            float* __restrict__ out) {
    __shared__ float2 W4sh[NHID];                       // [j] -> {W4[0][j], W4[1][j]}
    __shared__ unsigned short slist1[2][RPB][4][128];   // s1 index lists (per-warp segs)
    __shared__ unsigned short slist2[2][RPB][4][128];   // s2 index lists
    __shared__ int scnt1[2][RPB][4];
    __shared__ int scnt2[2][RPB][4];
    __shared__ float redx[2][RPB][4];                   // readout partials
    __shared__ float redy[2][RPB][4];

    const int tid = threadIdx.x;
    const int r = tid >> 7;                  // local row 0..3
    const int q = tid & 127;                 // neuron group 0..127
    const int n0 = q * 4;                    // global neurons n0..n0+3
    const int lane = tid & 31;
    const int wq = q >> 5;                   // warp within row 0..3
    const int rowg = blockIdx.x * RPB + r;   // global batch row

    W4sh[tid] = make_float2(W4[tid], W4[NHID + tid]);
    if (tid < 2 * RPB * 4) {
        ((int*)scnt1)[tid] = 0;
        ((int*)scnt2)[tid] = 0;
    }
    __syncthreads();

    const float4 t1v = *(const float4*)(tau1 + n0);
    const float4 v1v = *(const float4*)(Vth1 + n0);
    const float4 t2v = *(const float4*)(tau2 + n0);
    const float4 v2v = *(const float4*)(Vth2 + n0);
    float4 bias2;
    bias2.x = b2[n0 + 0] + br2[n0 + 0];
    bias2.y = b2[n0 + 1] + br2[n0 + 1];
    bias2.z = b2[n0 + 2] + br2[n0 + 2];
    bias2.w = b2[n0 + 3] + br2[n0 + 3];

    const float4 z4 = make_float4(0.f, 0.f, 0.f, 0.f);
    float4 mem1 = z4, sp1 = z4, cnt1 = z4;
    float4 mem2 = z4, sp2 = z4, cnt2 = z4;
    unsigned nib2_prev = 0u;                 // s2[t] nibble from previous phase
    float memo_x = 0.f, memo_y = 0.f;        // used by q==0 threads only
    const float to0 = tau_out[0], to1 = tau_out[1];
    const float b40 = b4[0], b41 = b4[1];

    const float4* __restrict__ Wa = g_Wa;
    const float4* __restrict__ Wb = g_Wb;

    // phase p: layer1 t=p (p<T), layer2 t=p-1 (1<=p<=T), readout t=p-2 (p>=2)
    for (int p = 0; p <= T_STEPS + 1; p++) {
        const int rb1 = (p + 1) & 1;         // buf holding s1[p-1]
        const int rb2 = p & 1;               // buf holding s2[p-2]

        // prefetch in1 row early
        float4 i1v = z4;
        if (p < T_STEPS)
            i1v = __ldcg((const float4*)(g_in1 + ((size_t)p * BATCH + rowg) * NHID + n0));

        // ---- combined pipelined walk over s1[p-1] list: a1 (Wr2) and f2 (W2) ----
        float4 a1 = z4, f2 = z4;
        if (p <= T_STEPS) {
#pragma unroll
            for (int w = 0; w < 4; w++) {
                const int c = scnt1[rb1][r][w];
                const unsigned short* __restrict__ L = slist1[rb1][r][w];
#pragma unroll 2
                for (int k = 0; k < c; k++) {
                    const int j = (int)L[k];
                    float4 wa = __ldg(Wa + ((j << 7) | q));
                    float4 wb = __ldg(Wb + ((j << 7) | q));
                    a1.x += wa.x; a1.y += wa.y; a1.z += wa.z; a1.w += wa.w;
                    f2.x += wb.x; f2.y += wb.y; f2.z += wb.z; f2.w += wb.w;
                }
            }
        }

        // ---- layer 1, t = p ----
        if (p < T_STEPS) {
            float4 i1 = i1v;
            i1.x += a1.x; i1.y += a1.y; i1.z += a1.z; i1.w += a1.w;
            mem1.x = t1v.x * mem1.x * (1.f - sp1.x) + i1.x;
            mem1.y = t1v.y * mem1.y * (1.f - sp1.y) + i1.y;
            mem1.z = t1v.z * mem1.z * (1.f - sp1.z) + i1.z;
            mem1.w = t1v.w * mem1.w * (1.f - sp1.w) + i1.w;
            float sx = (mem1.x > v1v.x) ? 1.f : 0.f;
            float sy = (mem1.y > v1v.y) ? 1.f : 0.f;
            float sz = (mem1.z > v1v.z) ? 1.f : 0.f;
            float sw = (mem1.w > v1v.w) ? 1.f : 0.f;
            sp1 = make_float4(sx, sy, sz, sw);
            cnt1.x += sx; cnt1.y += sy; cnt1.z += sz; cnt1.w += sw;
            unsigned nib = (sx > 0.f ? 1u : 0u) | (sy > 0.f ? 2u : 0u) |
                           (sz > 0.f ? 4u : 0u) | (sw > 0.f ? 8u : 0u);
            // warp-ordered compaction into per-warp segment (ascending j)
            int cme = __popc(nib);
            int scan = cme;
#pragma unroll
            for (int d = 1; d < 32; d <<= 1) {
                int v = __shfl_up_sync(0xffffffffu, scan, d);
                if (lane >= d) scan += v;
            }
            int base = scan - cme;
            unsigned m = nib;
            unsigned short* Lw = slist1[p & 1][r][wq];
            while (m) {
                int b = __ffs(m) - 1;
                m &= m - 1u;
                Lw[base++] = (unsigned short)(n0 + b);
            }
            if (lane == 31) scnt1[p & 1][r][wq] = scan;
        }

        // ---- layer 2, t = p-1 ----
        unsigned nib2_new = 0u;
        if (p >= 1 && p <= T_STEPS) {
            float4 r2 = z4;
#pragma unroll
            for (int w = 0; w < 4; w++) {
                const int c = scnt2[rb2][r][w];
                const unsigned short* __restrict__ L = slist2[rb2][r][w];
#pragma unroll 4
                for (int k = 0; k < c; k++) {
                    const int j = (int)L[k];
                    float4 wa = __ldg(Wa + ((j << 7) | q));
                    r2.x += wa.x; r2.y += wa.y; r2.z += wa.z; r2.w += wa.w;
                }
            }
            float4 i2;
            i2.x = f2.x + r2.x + bias2.x;
            i2.y = f2.y + r2.y + bias2.y;
            i2.z = f2.z + r2.z + bias2.z;
            i2.w = f2.w + r2.w + bias2.w;
            mem2.x = t2v.x * mem2.x * (1.f - sp2.x) + i2.x;
            mem2.y = t2v.y * mem2.y * (1.f - sp2.y) + i2.y;
            mem2.z = t2v.z * mem2.z * (1.f - sp2.z) + i2.z;
            mem2.w = t2v.w * mem2.w * (1.f - sp2.w) + i2.w;
            float sx = (mem2.x > v2v.x) ? 1.f : 0.f;
            float sy = (mem2.y > v2v.y) ? 1.f : 0.f;
            float sz = (mem2.z > v2v.z) ? 1.f : 0.f;
            float sw = (mem2.w > v2v.w) ? 1.f : 0.f;
            sp2 = make_float4(sx, sy, sz, sw);
            cnt2.x += sx; cnt2.y += sy; cnt2.z += sz; cnt2.w += sw;
            nib2_new = (sx > 0.f ? 1u : 0u) | (sy > 0.f ? 2u : 0u) |
                       (sz > 0.f ? 4u : 0u) | (sw > 0.f ? 8u : 0u);
            int cme = __popc(nib2_new);
            int scan = cme;
#pragma unroll
            for (int d = 1; d < 32; d <<= 1) {
                int v = __shfl_up_sync(0xffffffffu, scan, d);
                if (lane >= d) scan += v;
            }
            int base = scan - cme;
            unsigned m = nib2_new;
            unsigned short* Lw = slist2[(p + 1) & 1][r][wq];
            while (m) {
                int b = __ffs(m) - 1;
                m &= m - 1u;
                Lw[base++] = (unsigned short)(n0 + b);
            }
            if (lane == 31) scnt2[(p + 1) & 1][r][wq] = scan;
        }

        // ---- readout partials for t = p-2 (uses nib2_prev = s2[p-2]) ----
        {
            float ax = 0.f, ay = 0.f;
            unsigned nb = nib2_prev;
            if (nb & 1u) { float2 t = W4sh[n0 + 0]; ax += t.x; ay += t.y; }
            if (nb & 2u) { float2 t = W4sh[n0 + 1]; ax += t.x; ay += t.y; }
            if (nb & 4u) { float2 t = W4sh[n0 + 2]; ax += t.x; ay += t.y; }
            if (nb & 8u) { float2 t = W4sh[n0 + 3]; ax += t.x; ay += t.y; }
#pragma unroll
            for (int off = 16; off > 0; off >>= 1) {
                ax += __shfl_down_sync(0xffffffffu, ax, off);
                ay += __shfl_down_sync(0xffffffffu, ay, off);
            }
            if (lane == 0) {
                redx[p & 1][r][wq] = ax;
                redy[p & 1][r][wq] = ay;
            }
        }
        nib2_prev = nib2_new;

        __syncthreads();   // the ONLY sync per phase

        // ---- finalize readout t = p-2 ----
        if (p >= 2 && q == 0) {
            int par = p & 1;
            float ax = ((redx[par][r][0] + redx[par][r][1]) +
                        (redx[par][r][2] + redx[par][r][3]));
            float ay = ((redy[par][r][0] + redy[par][r][1]) +
                        (redy[par][r][2] + redy[par][r][3]));
            memo_x = to0 * memo_x + ax + b40;
            memo_y = to1 * memo_y + ay + b41;
            int t = p - 2;
            out[(size_t)rowg * (2 * T_STEPS) + t] = memo_x;
            out[(size_t)rowg * (2 * T_STEPS) + T_STEPS + t] = memo_y;
        }
    }

    // ---- spike-count outputs ----
    const float inv = 1.f / (float)T_STEPS;
    float* sc1 = out + (size_t)BATCH * 2 * T_STEPS;
    float* sc2 = sc1 + (size_t)BATCH * NHID;
    *(float4*)(sc1 + (size_t)rowg * NHID + n0) =
        make_float4(cnt1.x * inv, cnt1.y * inv, cnt1.z * inv, cnt1.w * inv);
    *(float4*)(sc2 + (size_t)rowg * NHID + n0) =
        make_float4(cnt2.x * inv, cnt2.y * inv, cnt2.z * inv, cnt2.w * inv);
}

// ---------------- launch ----------------------------------------------------------
extern "C" void kernel_launch(void* const* d_in, const int* in_sizes, int n_in,
                              void* d_out, int out_size) {
    (void)in_sizes; (void)n_in; (void)out_size;
    const float* x    = (const float*)d_in[0];
    const float* W1   = (const float*)d_in[1];
    const float* b1   = (const float*)d_in[2];
    const float* W2   = (const float*)d_in[3];
    const float* b2   = (const float*)d_in[4];
    const float* Wr2  = (const float*)d_in[5];
    const float* br2  = (const float*)d_in[6];
    // d_in[7..10]: W3, b3, Wr3, br3 — dead (layer 3 never reaches outputs)
    const float* W4   = (const float*)d_in[11];
    const float* b4   = (const float*)d_in[12];
    const float* Vth1 = (const float*)d_in[13];
    const float* tau1 = (const float*)d_in[14];
    const float* Vth2 = (const float*)d_in[15];
    const float* tau2 = (const float*)d_in[16];
    // d_in[17..18]: Vth3, tau3 — dead
    const float* tau_out = (const float*)d_in[19];
    float* out = (float*)d_out;

    k_transpose_x<<<dim3((T_STEPS + 31) / 32, CIN / 32, BATCH), dim3(32, 8)>>>(x);
    k_transpose_w1<<<dim3(CIN / 32, NHID / 32), dim3(32, 8)>>>(W1);
    k_pack<<<(NHID * 128) / 256, 256>>>(Wr2, W2);
    k_gemm_in1<<<dim3((T_STEPS * BATCH) / 128, NHID / 64), 256>>>(b1, br2);
    k_rsnn<<<NBLK, NT>>>(W4, b2, br2, b4, Vth1, tau1, Vth2, tau2, tau_out, out);
}

// round 6
// speedup vs baseline: 3.2390x; 1.1487x over previous
#include <cuda_runtime.h>
#include <cuda_bf16.h>
#include <cstdint>

#define T_STEPS 500
#define BATCH   512
#define CIN     128
#define NHID    512
#define NBLK    128          // independent blocks; 4 batch rows each
#define RPB     4
#define NT      512          // 128 threads per row; thread owns 4 neurons

// ---------------- static device scratch (no allocations allowed) ----------------
__device__ float g_xtr[(size_t)T_STEPS * BATCH * CIN];    // [(t*B+b)][c]
__device__ float g_in1[(size_t)T_STEPS * BATCH * NHID];   // x@W1^T + b1 + br2
__device__ float g_W1T[CIN * NHID];                       // [c][n]
// split gather tables: g_Wa[j*128+q] = Wr2[4q..4q+3][j], g_Wb likewise for W2
__device__ float4 g_Wa[(size_t)NHID * 128];
__device__ float4 g_Wb[(size_t)NHID * 128];

// ---------------- x[b][c][t] -> g_xtr[(t*B+b)][c] -------------------------------
__global__ void k_transpose_x(const float* __restrict__ x) {
    __shared__ float tile[32][33];
    int b = blockIdx.z;
    int t0 = blockIdx.x * 32, c0 = blockIdx.y * 32;
    int tx = threadIdx.x, ty = threadIdx.y;
#pragma unroll
    for (int i = 0; i < 32; i += 8) {
        int c = c0 + ty + i, t = t0 + tx;
        if (t < T_STEPS && c < CIN)
            tile[ty + i][tx] = x[((size_t)b * CIN + c) * T_STEPS + t];
    }
    __syncthreads();
#pragma unroll
    for (int i = 0; i < 32; i += 8) {
        int t = t0 + ty + i, c = c0 + tx;
        if (t < T_STEPS && c < CIN)
            g_xtr[((size_t)t * BATCH + b) * CIN + c] = tile[tx][ty + i];
    }
}

// ---------------- merged prep: W1 transpose + Wr2/W2 pack -------------------------
// blocks [0, 256): pack g_Wa/g_Wb.  blocks [256, 512): g_W1T.
__global__ void k_prep(const float* __restrict__ W1,
                       const float* __restrict__ Wr2, const float* __restrict__ W2) {
    int blk = blockIdx.x;
    if (blk < 256) {
        int i = blk * 256 + threadIdx.x;       // 0 .. 512*128-1
        int j = i >> 7, q = i & 127, n0 = q * 4;
        float4 a, b;
        a.x = Wr2[(size_t)(n0 + 0) * NHID + j];
        a.y = Wr2[(size_t)(n0 + 1) * NHID + j];
        a.z = Wr2[(size_t)(n0 + 2) * NHID + j];
        a.w = Wr2[(size_t)(n0 + 3) * NHID + j];
        b.x = W2[(size_t)(n0 + 0) * NHID + j];
        b.y = W2[(size_t)(n0 + 1) * NHID + j];
        b.z = W2[(size_t)(n0 + 2) * NHID + j];
        b.w = W2[(size_t)(n0 + 3) * NHID + j];
        g_Wa[i] = a;
        g_Wb[i] = b;
    } else {
        int i = (blk - 256) * 256 + threadIdx.x;   // 0 .. CIN*NHID-1
        int c = i >> 9, n = i & 511;
        g_W1T[(size_t)c * NHID + n] = W1[(size_t)n * CIN + c];
    }
}

// ---------------- in1 = xtr @ W1T + (b1 + br2); M=256000, K=128, N=512 -----------
// Identical FMA chains to previous rounds (bit-exact); only SMEM access widths changed.
__global__ __launch_bounds__(256)
void k_gemm_in1(const float* __restrict__ b1, const float* __restrict__ br2) {
    __shared__ float As[32][132];   // [k][m], padded to float4-aligned rows
    __shared__ float Bs[32][64];    // [k][n]
    const float* A = g_xtr;
    const float* B = g_W1T;
    int bm = blockIdx.x * 128, bn = blockIdx.y * 64;
    int tid = threadIdx.x;
    int tx = tid & 15, ty = tid >> 4;
    int arow = tid >> 3, acol = (tid & 7) * 4;
    int brow = tid >> 4, bcol = (tid & 15) * 4;

    float acc[8][4];
#pragma unroll
    for (int i = 0; i < 8; i++)
#pragma unroll
        for (int j = 0; j < 4; j++) acc[i][j] = 0.0f;

    for (int k0 = 0; k0 < CIN; k0 += 32) {
#pragma unroll
        for (int i = 0; i < 4; i++) {
            float4 v = *(const float4*)(A + (size_t)(bm + arow + 32 * i) * CIN + k0 + acol);
            As[acol + 0][arow + 32 * i] = v.x;
            As[acol + 1][arow + 32 * i] = v.y;
            As[acol + 2][arow + 32 * i] = v.z;
            As[acol + 3][arow + 32 * i] = v.w;
        }
#pragma unroll
        for (int i = 0; i < 2; i++) {
            *(float4*)&Bs[brow + 16 * i][bcol] =
                *(const float4*)(B + (size_t)(k0 + brow + 16 * i) * NHID + bn + bcol);
        }
        __syncthreads();
#pragma unroll
        for (int k = 0; k < 32; k++) {
            // vectorized A-fragment read: a[0..7] = As[k][ty*8 .. ty*8+7]
            float4 av0 = *(const float4*)&As[k][ty * 8];
            float4 av1 = *(const float4*)&As[k][ty * 8 + 4];
            float a[8];
            a[0] = av0.x; a[1] = av0.y; a[2] = av0.z; a[3] = av0.w;
            a[4] = av1.x; a[5] = av1.y; a[6] = av1.z; a[7] = av1.w;
            float4 bv = *(const float4*)&Bs[k][tx * 4];
#pragma unroll
            for (int i = 0; i < 8; i++) {
                acc[i][0] += a[i] * bv.x;
                acc[i][1] += a[i] * bv.y;
                acc[i][2] += a[i] * bv.z;
                acc[i][3] += a[i] * bv.w;
            }
        }
        __syncthreads();
    }
    int col = bn + tx * 4;
    float bb0 = b1[col + 0] + br2[col + 0];
    float bb1 = b1[col + 1] + br2[col + 1];
    float bb2 = b1[col + 2] + br2[col + 2];
    float bb3 = b1[col + 3] + br2[col + 3];
#pragma unroll
    for (int i = 0; i < 8; i++) {
        size_t row = (size_t)(bm + ty * 8 + i);
        float4 o;
        o.x = acc[i][0] + bb0;
        o.y = acc[i][1] + bb1;
        o.z = acc[i][2] + bb2;
        o.w = acc[i][3] + bb3;
        *(float4*)(g_in1 + row * NHID + bn + tx * 4) = o;
    }
}

// ---------------- persistent per-block recurrent kernel (no grid sync) -----------
__global__ __launch_bounds__(NT, 1)
void k_rsnn(const float* __restrict__ W4,
            const float* __restrict__ b2, const float* __restrict__ br2,
            const float* __restrict__ b4,
            const float* __restrict__ Vth1, const float* __restrict__ tau1,
            const float* __restrict__ Vth2, const float* __restrict__ tau2,
            const float* __restrict__ tau_out,
            float* __restrict__ out) {
    __shared__ float2 W4sh[NHID];                       // [j] -> {W4[0][j], W4[1][j]}
    __shared__ unsigned short slist1[2][RPB][4][128];   // s1 index lists (per-warp segs)
    __shared__ unsigned short slist2[2][RPB][4][128];   // s2 index lists
    __shared__ int scnt1[2][RPB][4];
    __shared__ int scnt2[2][RPB][4];
    __shared__ float redx[2][RPB][4];                   // readout partials
    __shared__ float redy[2][RPB][4];

    const int tid = threadIdx.x;
    const int r = tid >> 7;                  // local row 0..3
    const int q = tid & 127;                 // neuron group 0..127
    const int n0 = q * 4;                    // global neurons n0..n0+3
    const int lane = tid & 31;
    const int wq = q >> 5;                   // warp within row 0..3
    const int rowg = blockIdx.x * RPB + r;   // global batch row

    W4sh[tid] = make_float2(W4[tid], W4[NHID + tid]);
    if (tid < 2 * RPB * 4) {
        ((int*)scnt1)[tid] = 0;
        ((int*)scnt2)[tid] = 0;
    }
    __syncthreads();

    const float4 t1v = *(const float4*)(tau1 + n0);
    const float4 v1v = *(const float4*)(Vth1 + n0);
    const float4 t2v = *(const float4*)(tau2 + n0);
    const float4 v2v = *(const float4*)(Vth2 + n0);
    float4 bias2;
    bias2.x = b2[n0 + 0] + br2[n0 + 0];
    bias2.y = b2[n0 + 1] + br2[n0 + 1];
    bias2.z = b2[n0 + 2] + br2[n0 + 2];
    bias2.w = b2[n0 + 3] + br2[n0 + 3];

    const float4 z4 = make_float4(0.f, 0.f, 0.f, 0.f);
    float4 mem1 = z4, sp1 = z4, cnt1 = z4;
    float4 mem2 = z4, sp2 = z4, cnt2 = z4;
    unsigned nib2_prev = 0u;                 // s2[t] nibble from previous phase
    float memo_x = 0.f, memo_y = 0.f;        // used by q==0 threads only
    const float to0 = tau_out[0], to1 = tau_out[1];
    const float b40 = b4[0], b41 = b4[1];

    const float4* __restrict__ Wa = g_Wa;
    const float4* __restrict__ Wb = g_Wb;

    // phase p: layer1 t=p (p<T), layer2 t=p-1 (1<=p<=T), readout t=p-2 (p>=2)
    for (int p = 0; p <= T_STEPS + 1; p++) {
        const int rb1 = (p + 1) & 1;         // buf holding s1[p-1]
        const int rb2 = p & 1;               // buf holding s2[p-2]

        // prefetch in1 row early
        float4 i1v = z4;
        if (p < T_STEPS)
            i1v = __ldcg((const float4*)(g_in1 + ((size_t)p * BATCH + rowg) * NHID + n0));

        // ---- combined pipelined walk over s1[p-1] list: a1 (Wr2) and f2 (W2) ----
        float4 a1 = z4, f2 = z4;
        if (p <= T_STEPS) {
#pragma unroll
            for (int w = 0; w < 4; w++) {
                const int c = scnt1[rb1][r][w];
                const unsigned short* __restrict__ L = slist1[rb1][r][w];
#pragma unroll 4
                for (int k = 0; k < c; k++) {
                    const int j = (int)L[k];
                    float4 wa = __ldg(Wa + ((j << 7) | q));
                    float4 wb = __ldg(Wb + ((j << 7) | q));
                    a1.x += wa.x; a1.y += wa.y; a1.z += wa.z; a1.w += wa.w;
                    f2.x += wb.x; f2.y += wb.y; f2.z += wb.z; f2.w += wb.w;
                }
            }
        }

        // ---- layer 1, t = p ----
        if (p < T_STEPS) {
            float4 i1 = i1v;
            i1.x += a1.x; i1.y += a1.y; i1.z += a1.z; i1.w += a1.w;
            mem1.x = t1v.x * mem1.x * (1.f - sp1.x) + i1.x;
            mem1.y = t1v.y * mem1.y * (1.f - sp1.y) + i1.y;
            mem1.z = t1v.z * mem1.z * (1.f - sp1.z) + i1.z;
            mem1.w = t1v.w * mem1.w * (1.f - sp1.w) + i1.w;
            float sx = (mem1.x > v1v.x) ? 1.f : 0.f;
            float sy = (mem1.y > v1v.y) ? 1.f : 0.f;
            float sz = (mem1.z > v1v.z) ? 1.f : 0.f;
            float sw = (mem1.w > v1v.w) ? 1.f : 0.f;
            sp1 = make_float4(sx, sy, sz, sw);
            cnt1.x += sx; cnt1.y += sy; cnt1.z += sz; cnt1.w += sw;
            unsigned nib = (sx > 0.f ? 1u : 0u) | (sy > 0.f ? 2u : 0u) |
                           (sz > 0.f ? 4u : 0u) | (sw > 0.f ? 8u : 0u);
            // warp-ordered compaction into per-warp segment (ascending j)
            int cme = __popc(nib);
            int scan = cme;
#pragma unroll
            for (int d = 1; d < 32; d <<= 1) {
                int v = __shfl_up_sync(0xffffffffu, scan, d);
                if (lane >= d) scan += v;
            }
            int base = scan - cme;
            unsigned m = nib;
            unsigned short* Lw = slist1[p & 1][r][wq];
            while (m) {
                int b = __ffs(m) - 1;
                m &= m - 1u;
                Lw[base++] = (unsigned short)(n0 + b);
            }
            if (lane == 31) scnt1[p & 1][r][wq] = scan;
        }

        // ---- layer 2, t = p-1 ----
        unsigned nib2_new = 0u;
        if (p >= 1 && p <= T_STEPS) {
            float4 r2 = z4;
#pragma unroll
            for (int w = 0; w < 4; w++) {
                const int c = scnt2[rb2][r][w];
                const unsigned short* __restrict__ L = slist2[rb2][r][w];
#pragma unroll 4
                for (int k = 0; k < c; k++) {
                    const int j = (int)L[k];
                    float4 wa = __ldg(Wa + ((j << 7) | q));
                    r2.x += wa.x; r2.y += wa.y; r2.z += wa.z; r2.w += wa.w;
                }
            }
            float4 i2;
            i2.x = f2.x + r2.x + bias2.x;
            i2.y = f2.y + r2.y + bias2.y;
            i2.z = f2.z + r2.z + bias2.z;
            i2.w = f2.w + r2.w + bias2.w;
            mem2.x = t2v.x * mem2.x * (1.f - sp2.x) + i2.x;
            mem2.y = t2v.y * mem2.y * (1.f - sp2.y) + i2.y;
            mem2.z = t2v.z * mem2.z * (1.f - sp2.z) + i2.z;
            mem2.w = t2v.w * mem2.w * (1.f - sp2.w) + i2.w;
            float sx = (mem2.x > v2v.x) ? 1.f : 0.f;
            float sy = (mem2.y > v2v.y) ? 1.f : 0.f;
            float sz = (mem2.z > v2v.z) ? 1.f : 0.f;
            float sw = (mem2.w > v2v.w) ? 1.f : 0.f;
            sp2 = make_float4(sx, sy, sz, sw);
            cnt2.x += sx; cnt2.y += sy; cnt2.z += sz; cnt2.w += sw;
            nib2_new = (sx > 0.f ? 1u : 0u) | (sy > 0.f ? 2u : 0u) |
                       (sz > 0.f ? 4u : 0u) | (sw > 0.f ? 8u : 0u);
            int cme = __popc(nib2_new);
            int scan = cme;
#pragma unroll
            for (int d = 1; d < 32; d <<= 1) {
                int v = __shfl_up_sync(0xffffffffu, scan, d);
                if (lane >= d) scan += v;
            }
            int base = scan - cme;
            unsigned m = nib2_new;
            unsigned short* Lw = slist2[(p + 1) & 1][r][wq];
            while (m) {
                int b = __ffs(m) - 1;
                m &= m - 1u;
                Lw[base++] = (unsigned short)(n0 + b);
            }
            if (lane == 31) scnt2[(p + 1) & 1][r][wq] = scan;
        }

        // ---- readout partials for t = p-2 (uses nib2_prev = s2[p-2]) ----
        {
            float ax = 0.f, ay = 0.f;
            unsigned nb = nib2_prev;
            if (nb & 1u) { float2 t = W4sh[n0 + 0]; ax += t.x; ay += t.y; }
            if (nb & 2u) { float2 t = W4sh[n0 + 1]; ax += t.x; ay += t.y; }
            if (nb & 4u) { float2 t = W4sh[n0 + 2]; ax += t.x; ay += t.y; }
            if (nb & 8u) { float2 t = W4sh[n0 + 3]; ax += t.x; ay += t.y; }
#pragma unroll
            for (int off = 16; off > 0; off >>= 1) {
                ax += __shfl_down_sync(0xffffffffu, ax, off);
                ay += __shfl_down_sync(0xffffffffu, ay, off);
            }
            if (lane == 0) {
                redx[p & 1][r][wq] = ax;
                redy[p & 1][r][wq] = ay;
            }
        }
        nib2_prev = nib2_new;

        __syncthreads();   // the ONLY sync per phase

        // ---- finalize readout t = p-2 ----
        if (p >= 2 && q == 0) {
            int par = p & 1;
            float ax = ((redx[par][r][0] + redx[par][r][1]) +
                        (redx[par][r][2] + redx[par][r][3]));
            float ay = ((redy[par][r][0] + redy[par][r][1]) +
                        (redy[par][r][2] + redy[par][r][3]));
            memo_x = to0 * memo_x + ax + b40;
            memo_y = to1 * memo_y + ay + b41;
            int t = p - 2;
            out[(size_t)rowg * (2 * T_STEPS) + t] = memo_x;
            out[(size_t)rowg * (2 * T_STEPS) + T_STEPS + t] = memo_y;
        }
    }

    // ---- spike-count outputs ----
    const float inv = 1.f / (float)T_STEPS;
    float* sc1 = out + (size_t)BATCH * 2 * T_STEPS;
    float* sc2 = sc1 + (size_t)BATCH * NHID;
    *(float4*)(sc1 + (size_t)rowg * NHID + n0) =
        make_float4(cnt1.x * inv, cnt1.y * inv, cnt1.z * inv, cnt1.w * inv);
    *(float4*)(sc2 + (size_t)rowg * NHID + n0) =
        make_float4(cnt2.x * inv, cnt2.y * inv, cnt2.z * inv, cnt2.w * inv);
}

// ---------------- launch ----------------------------------------------------------
extern "C" void kernel_launch(void* const* d_in, const int* in_sizes, int n_in,
                              void* d_out, int out_size) {
    (void)in_sizes; (void)n_in; (void)out_size;
    const float* x    = (const float*)d_in[0];
    const float* W1   = (const float*)d_in[1];
    const float* b1   = (const float*)d_in[2];
    const float* W2   = (const float*)d_in[3];
    const float* b2   = (const float*)d_in[4];
    const float* Wr2  = (const float*)d_in[5];
    const float* br2  = (const float*)d_in[6];
    // d_in[7..10]: W3, b3, Wr3, br3 — dead (layer 3 never reaches outputs)
    const float* W4   = (const float*)d_in[11];
    const float* b4   = (const float*)d_in[12];
    const float* Vth1 = (const float*)d_in[13];
    const float* tau1 = (const float*)d_in[14];
    const float* Vth2 = (const float*)d_in[15];
    const float* tau2 = (const float*)d_in[16];
    // d_in[17..18]: Vth3, tau3 — dead
    const float* tau_out = (const float*)d_in[19];
    float* out = (float*)d_out;

    k_transpose_x<<<dim3((T_STEPS + 31) / 32, CIN / 32, BATCH), dim3(32, 8)>>>(x);
    k_prep<<<512, 256>>>(W1, Wr2, W2);
    k_gemm_in1<<<dim3((T_STEPS * BATCH) / 128, NHID / 64), 256>>>(b1, br2);
    k_rsnn<<<NBLK, NT>>>(W4, b2, br2, b4, Vth1, tau1, Vth2, tau2, tau_out, out);
}

// round 7
// speedup vs baseline: 3.3549x; 1.0358x over previous
#include <cuda_runtime.h>
#include <cuda_bf16.h>
#include <cstdint>

#define T_STEPS 500
#define BATCH   512
#define CIN     128
#define NHID    512
#define NBLK    128          // independent blocks; 4 batch rows each
#define RPB     4
#define NT      512          // 128 threads per row; thread owns 4 neurons
#define ZROW    512          // sentinel row index (all zeros) for list padding

// ---------------- static device scratch (no allocations allowed) ----------------
__device__ float g_xtr[(size_t)T_STEPS * BATCH * CIN];    // [(t*B+b)][c]
__device__ float g_in1[(size_t)T_STEPS * BATCH * NHID];   // x@W1^T + b1 + br2
__device__ float g_W1T[CIN * NHID];                       // [c][n]
// combined gather table: per j (row of 1024 floats):
//   [q*4 .. q*4+3]        = Wr2[4q..4q+3][j]
//   [512 + q*4 .. +3]     = W2 [4q..4q+3][j]
// rows j = 512..515 stay zero (sentinel padding rows; .bss zero-init, never written)
__device__ float g_Wab[(size_t)(ZROW + 4) * 1024];

// ---------------- x[b][c][t] -> g_xtr[(t*B+b)][c] -------------------------------
__global__ void k_transpose_x(const float* __restrict__ x) {
    __shared__ float tile[32][33];
    int b = blockIdx.z;
    int t0 = blockIdx.x * 32, c0 = blockIdx.y * 32;
    int tx = threadIdx.x, ty = threadIdx.y;
#pragma unroll
    for (int i = 0; i < 32; i += 8) {
        int c = c0 + ty + i, t = t0 + tx;
        if (t < T_STEPS && c < CIN)
            tile[ty + i][tx] = x[((size_t)b * CIN + c) * T_STEPS + t];
    }
    __syncthreads();
#pragma unroll
    for (int i = 0; i < 32; i += 8) {
        int t = t0 + ty + i, c = c0 + tx;
        if (t < T_STEPS && c < CIN)
            g_xtr[((size_t)t * BATCH + b) * CIN + c] = tile[tx][ty + i];
    }
}

// ---------------- merged prep: W1 transpose + Wab pack ----------------------------
__global__ void k_prep(const float* __restrict__ W1,
                       const float* __restrict__ Wr2, const float* __restrict__ W2) {
    int blk = blockIdx.x;
    if (blk < 256) {
        int i = blk * 256 + threadIdx.x;       // 0 .. 512*128-1
        int j = i >> 7, q = i & 127, n0 = q * 4;
        float4 a, b;
        a.x = Wr2[(size_t)(n0 + 0) * NHID + j];
        a.y = Wr2[(size_t)(n0 + 1) * NHID + j];
        a.z = Wr2[(size_t)(n0 + 2) * NHID + j];
        a.w = Wr2[(size_t)(n0 + 3) * NHID + j];
        b.x = W2[(size_t)(n0 + 0) * NHID + j];
        b.y = W2[(size_t)(n0 + 1) * NHID + j];
        b.z = W2[(size_t)(n0 + 2) * NHID + j];
        b.w = W2[(size_t)(n0 + 3) * NHID + j];
        *(float4*)(g_Wab + (size_t)j * 1024 + q * 4) = a;
        *(float4*)(g_Wab + (size_t)j * 1024 + 512 + q * 4) = b;
    } else {
        int i = (blk - 256) * 256 + threadIdx.x;   // 0 .. CIN*NHID-1
        int c = i >> 9, n = i & 511;
        g_W1T[(size_t)c * NHID + n] = W1[(size_t)n * CIN + c];
    }
}

// ---------------- in1 = xtr @ W1T + (b1 + br2); 128x128 tile, 8x8/thread ---------
// Per-output-element accumulation order over k is unchanged (ascending 0..127)
// and bias added once at the end -> bit-exact vs previous rounds.
__global__ __launch_bounds__(256)
void k_gemm_in1(const float* __restrict__ b1, const float* __restrict__ br2) {
    __shared__ float As[16][132];   // [k][m]
    __shared__ float Bs[16][132];   // [k][n]
    const float* A = g_xtr;
    const float* B = g_W1T;
    int bm = blockIdx.x * 128, bn = blockIdx.y * 128;
    int tid = threadIdx.x;
    int tx = tid & 15, ty = tid >> 4;
    int arow = tid >> 1, acol = (tid & 1) * 8;   // A: one row-half per thread
    int brow = tid >> 4, bcol = (tid & 15) * 8;  // B: 16 rows x 128 cols

    float acc[8][8];
#pragma unroll
    for (int i = 0; i < 8; i++)
#pragma unroll
        for (int j = 0; j < 8; j++) acc[i][j] = 0.0f;

    for (int k0 = 0; k0 < CIN; k0 += 16) {
        float4 v0 = *(const float4*)(A + (size_t)(bm + arow) * CIN + k0 + acol);
        float4 v1 = *(const float4*)(A + (size_t)(bm + arow) * CIN + k0 + acol + 4);
        As[acol + 0][arow] = v0.x;
        As[acol + 1][arow] = v0.y;
        As[acol + 2][arow] = v0.z;
        As[acol + 3][arow] = v0.w;
        As[acol + 4][arow] = v1.x;
        As[acol + 5][arow] = v1.y;
        As[acol + 6][arow] = v1.z;
        As[acol + 7][arow] = v1.w;
        *(float4*)&Bs[brow][bcol] =
            *(const float4*)(B + (size_t)(k0 + brow) * NHID + bn + bcol);
        *(float4*)&Bs[brow][bcol + 4] =
            *(const float4*)(B + (size_t)(k0 + brow) * NHID + bn + bcol + 4);
        __syncthreads();
#pragma unroll
        for (int k = 0; k < 16; k++) {
            float4 av0 = *(const float4*)&As[k][ty * 8];
            float4 av1 = *(const float4*)&As[k][ty * 8 + 4];
            float4 bv0 = *(const float4*)&Bs[k][tx * 4];
            float4 bv1 = *(const float4*)&Bs[k][64 + tx * 4];
            float a[8] = {av0.x, av0.y, av0.z, av0.w, av1.x, av1.y, av1.z, av1.w};
            float b[8] = {bv0.x, bv0.y, bv0.z, bv0.w, bv1.x, bv1.y, bv1.z, bv1.w};
#pragma unroll
            for (int i = 0; i < 8; i++) {
#pragma unroll
                for (int j = 0; j < 8; j++) acc[i][j] += a[i] * b[j];
            }
        }
        __syncthreads();
    }
    int col0 = bn + tx * 4;
    int col1 = bn + 64 + tx * 4;
    float bb[8];
#pragma unroll
    for (int j = 0; j < 4; j++) {
        bb[j] = b1[col0 + j] + br2[col0 + j];
        bb[4 + j] = b1[col1 + j] + br2[col1 + j];
    }
#pragma unroll
    for (int i = 0; i < 8; i++) {
        size_t row = (size_t)(bm + ty * 8 + i);
        float4 o0, o1;
        o0.x = acc[i][0] + bb[0];
        o0.y = acc[i][1] + bb[1];
        o0.z = acc[i][2] + bb[2];
        o0.w = acc[i][3] + bb[3];
        o1.x = acc[i][4] + bb[4];
        o1.y = acc[i][5] + bb[5];
        o1.z = acc[i][6] + bb[6];
        o1.w = acc[i][7] + bb[7];
        *(float4*)(g_in1 + row * NHID + col0) = o0;
        *(float4*)(g_in1 + row * NHID + col1) = o1;
    }
}

// ---------------- chunked walks (lists padded to x4 with ZROW sentinels) ---------
__device__ __forceinline__ void walk_dual(const unsigned short* __restrict__ L, int c,
                                          const float* __restrict__ WAB, int q4,
                                          float4& a1, float4& f2) {
    for (int k = 0; k < c; k += 4) {
        ushort4 jj = *(const ushort4*)(L + k);
        const float* p0 = WAB + ((int)jj.x << 10) + q4;
        const float* p1 = WAB + ((int)jj.y << 10) + q4;
        const float* p2 = WAB + ((int)jj.z << 10) + q4;
        const float* p3 = WAB + ((int)jj.w << 10) + q4;
        float4 a0 = __ldg((const float4*)p0);
        float4 b0 = __ldg((const float4*)(p0 + 512));
        float4 a1r = __ldg((const float4*)p1);
        float4 b1r = __ldg((const float4*)(p1 + 512));
        float4 a2 = __ldg((const float4*)p2);
        float4 b2 = __ldg((const float4*)(p2 + 512));
        float4 a3 = __ldg((const float4*)p3);
        float4 b3 = __ldg((const float4*)(p3 + 512));
        // ascending j order; sentinel rows are zeros (x + 0.0f bit-exact)
        a1.x += a0.x; a1.y += a0.y; a1.z += a0.z; a1.w += a0.w;
        f2.x += b0.x; f2.y += b0.y; f2.z += b0.z; f2.w += b0.w;
        a1.x += a1r.x; a1.y += a1r.y; a1.z += a1r.z; a1.w += a1r.w;
        f2.x += b1r.x; f2.y += b1r.y; f2.z += b1r.z; f2.w += b1r.w;
        a1.x += a2.x; a1.y += a2.y; a1.z += a2.z; a1.w += a2.w;
        f2.x += b2.x; f2.y += b2.y; f2.z += b2.z; f2.w += b2.w;
        a1.x += a3.x; a1.y += a3.y; a1.z += a3.z; a1.w += a3.w;
        f2.x += b3.x; f2.y += b3.y; f2.z += b3.z; f2.w += b3.w;
    }
}

__device__ __forceinline__ void walk_single(const unsigned short* __restrict__ L, int c,
                                            const float* __restrict__ WAB, int q4,
                                            float4& r2) {
    for (int k = 0; k < c; k += 4) {
        ushort4 jj = *(const ushort4*)(L + k);
        float4 a0 = __ldg((const float4*)(WAB + ((int)jj.x << 10) + q4));
        float4 a1r = __ldg((const float4*)(WAB + ((int)jj.y << 10) + q4));
        float4 a2 = __ldg((const float4*)(WAB + ((int)jj.z << 10) + q4));
        float4 a3 = __ldg((const float4*)(WAB + ((int)jj.w << 10) + q4));
        r2.x += a0.x; r2.y += a0.y; r2.z += a0.z; r2.w += a0.w;
        r2.x += a1r.x; r2.y += a1r.y; r2.z += a1r.z; r2.w += a1r.w;
        r2.x += a2.x; r2.y += a2.y; r2.z += a2.z; r2.w += a2.w;
        r2.x += a3.x; r2.y += a3.y; r2.z += a3.z; r2.w += a3.w;
    }
}

// ---------------- persistent per-block recurrent kernel (no grid sync) -----------
__global__ __launch_bounds__(NT, 1)
void k_rsnn(const float* __restrict__ W4,
            const float* __restrict__ b2, const float* __restrict__ br2,
            const float* __restrict__ b4,
            const float* __restrict__ Vth1, const float* __restrict__ tau1,
            const float* __restrict__ Vth2, const float* __restrict__ tau2,
            const float* __restrict__ tau_out,
            float* __restrict__ out) {
    __shared__ float2 W4sh[NHID];
    __shared__ __align__(16) unsigned short slist1[2][RPB][4][128];
    __shared__ __align__(16) unsigned short slist2[2][RPB][4][128];
    __shared__ int scnt1[2][RPB][4];   // padded counts (multiple of 4)
    __shared__ int scnt2[2][RPB][4];
    __shared__ float redx[2][RPB][4];
    __shared__ float redy[2][RPB][4];

    const int tid = threadIdx.x;
    const int r = tid >> 7;                  // local row 0..3
    const int q = tid & 127;                 // neuron group 0..127
    const int n0 = q * 4;
    const int q4 = q * 4;
    const int lane = tid & 31;
    const int wq = q >> 5;                   // warp within row 0..3
    const int rowg = blockIdx.x * RPB + r;

    W4sh[tid] = make_float2(W4[tid], W4[NHID + tid]);
    if (tid < 2 * RPB * 4) {
        ((int*)scnt1)[tid] = 0;
        ((int*)scnt2)[tid] = 0;
    }
    __syncthreads();

    const float4 t1v = *(const float4*)(tau1 + n0);
    const float4 v1v = *(const float4*)(Vth1 + n0);
    const float4 t2v = *(const float4*)(tau2 + n0);
    const float4 v2v = *(const float4*)(Vth2 + n0);
    float4 bias2;
    bias2.x = b2[n0 + 0] + br2[n0 + 0];
    bias2.y = b2[n0 + 1] + br2[n0 + 1];
    bias2.z = b2[n0 + 2] + br2[n0 + 2];
    bias2.w = b2[n0 + 3] + br2[n0 + 3];

    const float4 z4 = make_float4(0.f, 0.f, 0.f, 0.f);
    float4 mem1 = z4, sp1 = z4, cnt1 = z4;
    float4 mem2 = z4, sp2 = z4, cnt2 = z4;
    unsigned nib2_prev = 0u;
    float memo_x = 0.f, memo_y = 0.f;
    const float to0 = tau_out[0], to1 = tau_out[1];
    const float b40 = b4[0], b41 = b4[1];

    const float* __restrict__ WAB = g_Wab;

    for (int p = 0; p <= T_STEPS + 1; p++) {
        const int rb1 = (p + 1) & 1;         // buf holding s1[p-1]
        const int rb2 = p & 1;               // buf holding s2[p-2]

        float4 i1v = z4;
        if (p < T_STEPS)
            i1v = __ldcg((const float4*)(g_in1 + ((size_t)p * BATCH + rowg) * NHID + n0));

        // ---- combined walk over s1[p-1]: a1 (Wr2) and f2 (W2) ----
        float4 a1 = z4, f2 = z4;
        if (p <= T_STEPS) {
#pragma unroll
            for (int w = 0; w < 4; w++)
                walk_dual(slist1[rb1][r][w], scnt1[rb1][r][w], WAB, q4, a1, f2);
        }

        // ---- layer 1, t = p ----
        if (p < T_STEPS) {
            float4 i1 = i1v;
            i1.x += a1.x; i1.y += a1.y; i1.z += a1.z; i1.w += a1.w;
            mem1.x = t1v.x * mem1.x * (1.f - sp1.x) + i1.x;
            mem1.y = t1v.y * mem1.y * (1.f - sp1.y) + i1.y;
            mem1.z = t1v.z * mem1.z * (1.f - sp1.z) + i1.z;
            mem1.w = t1v.w * mem1.w * (1.f - sp1.w) + i1.w;
            float sx = (mem1.x > v1v.x) ? 1.f : 0.f;
            float sy = (mem1.y > v1v.y) ? 1.f : 0.f;
            float sz = (mem1.z > v1v.z) ? 1.f : 0.f;
            float sw = (mem1.w > v1v.w) ? 1.f : 0.f;
            sp1 = make_float4(sx, sy, sz, sw);
            cnt1.x += sx; cnt1.y += sy; cnt1.z += sz; cnt1.w += sw;
            unsigned nib = (sx > 0.f ? 1u : 0u) | (sy > 0.f ? 2u : 0u) |
                           (sz > 0.f ? 4u : 0u) | (sw > 0.f ? 8u : 0u);
            int cme = __popc(nib);
            int scan = cme;
#pragma unroll
            for (int d = 1; d < 32; d <<= 1) {
                int v = __shfl_up_sync(0xffffffffu, scan, d);
                if (lane >= d) scan += v;
            }
            int base = scan - cme;
            unsigned m = nib;
            unsigned short* Lw = slist1[p & 1][r][wq];
            while (m) {
                int b = __ffs(m) - 1;
                m &= m - 1u;
                Lw[base++] = (unsigned short)(n0 + b);
            }
            int ctot = __shfl_sync(0xffffffffu, scan, 31);
            int cpad = (ctot + 3) & ~3;
            if (lane < cpad - ctot) Lw[ctot + lane] = (unsigned short)ZROW;
            if (lane == 31) scnt1[p & 1][r][wq] = cpad;
        }

        // ---- layer 2, t = p-1 ----
        unsigned nib2_new = 0u;
        if (p >= 1 && p <= T_STEPS) {
            float4 r2 = z4;
#pragma unroll
            for (int w = 0; w < 4; w++)
                walk_single(slist2[rb2][r][w], scnt2[rb2][r][w], WAB, q4, r2);
            float4 i2;
            i2.x = f2.x + r2.x + bias2.x;
            i2.y = f2.y + r2.y + bias2.y;
            i2.z = f2.z + r2.z + bias2.z;
            i2.w = f2.w + r2.w + bias2.w;
            mem2.x = t2v.x * mem2.x * (1.f - sp2.x) + i2.x;
            mem2.y = t2v.y * mem2.y * (1.f - sp2.y) + i2.y;
            mem2.z = t2v.z * mem2.z * (1.f - sp2.z) + i2.z;
            mem2.w = t2v.w * mem2.w * (1.f - sp2.w) + i2.w;
            float sx = (mem2.x > v2v.x) ? 1.f : 0.f;
            float sy = (mem2.y > v2v.y) ? 1.f : 0.f;
            float sz = (mem2.z > v2v.z) ? 1.f : 0.f;
            float sw = (mem2.w > v2v.w) ? 1.f : 0.f;
            sp2 = make_float4(sx, sy, sz, sw);
            cnt2.x += sx; cnt2.y += sy; cnt2.z += sz; cnt2.w += sw;
            nib2_new = (sx > 0.f ? 1u : 0u) | (sy > 0.f ? 2u : 0u) |
                       (sz > 0.f ? 4u : 0u) | (sw > 0.f ? 8u : 0u);
            int cme = __popc(nib2_new);
            int scan = cme;
#pragma unroll
            for (int d = 1; d < 32; d <<= 1) {
                int v = __shfl_up_sync(0xffffffffu, scan, d);
                if (lane >= d) scan += v;
            }
            int base = scan - cme;
            unsigned m = nib2_new;
            unsigned short* Lw = slist2[(p + 1) & 1][r][wq];
            while (m) {
                int b = __ffs(m) - 1;
                m &= m - 1u;
                Lw[base++] = (unsigned short)(n0 + b);
            }
            int ctot = __shfl_sync(0xffffffffu, scan, 31);
            int cpad = (ctot + 3) & ~3;
            if (lane < cpad - ctot) Lw[ctot + lane] = (unsigned short)ZROW;
            if (lane == 31) scnt2[(p + 1) & 1][r][wq] = cpad;
        }

        // ---- readout partials for t = p-2 (uses nib2_prev = s2[p-2]) ----
        {
            float ax = 0.f, ay = 0.f;
            unsigned nb = nib2_prev;
            if (nb & 1u) { float2 t = W4sh[n0 + 0]; ax += t.x; ay += t.y; }
            if (nb & 2u) { float2 t = W4sh[n0 + 1]; ax += t.x; ay += t.y; }
            if (nb & 4u) { float2 t = W4sh[n0 + 2]; ax += t.x; ay += t.y; }
            if (nb & 8u) { float2 t = W4sh[n0 + 3]; ax += t.x; ay += t.y; }
#pragma unroll
            for (int off = 16; off > 0; off >>= 1) {
                ax += __shfl_down_sync(0xffffffffu, ax, off);
                ay += __shfl_down_sync(0xffffffffu, ay, off);
            }
            if (lane == 0) {
                redx[p & 1][r][wq] = ax;
                redy[p & 1][r][wq] = ay;
            }
        }
        nib2_prev = nib2_new;

        __syncthreads();   // the ONLY sync per phase

        // ---- finalize readout t = p-2 ----
        if (p >= 2 && q == 0) {
            int par = p & 1;
            float ax = ((redx[par][r][0] + redx[par][r][1]) +
                        (redx[par][r][2] + redx[par][r][3]));
            float ay = ((redy[par][r][0] + redy[par][r][1]) +
                        (redy[par][r][2] + redy[par][r][3]));
            memo_x = to0 * memo_x + ax + b40;
            memo_y = to1 * memo_y + ay + b41;
            int t = p - 2;
            out[(size_t)rowg * (2 * T_STEPS) + t] = memo_x;
            out[(size_t)rowg * (2 * T_STEPS) + T_STEPS + t] = memo_y;
        }
    }

    // ---- spike-count outputs ----
    const float inv = 1.f / (float)T_STEPS;
    float* sc1 = out + (size_t)BATCH * 2 * T_STEPS;
    float* sc2 = sc1 + (size_t)BATCH * NHID;
    *(float4*)(sc1 + (size_t)rowg * NHID + n0) =
        make_float4(cnt1.x * inv, cnt1.y * inv, cnt1.z * inv, cnt1.w * inv);
    *(float4*)(sc2 + (size_t)rowg * NHID + n0) =
        make_float4(cnt2.x * inv, cnt2.y * inv, cnt2.z * inv, cnt2.w * inv);
}

// ---------------- launch ----------------------------------------------------------
extern "C" void kernel_launch(void* const* d_in, const int* in_sizes, int n_in,
                              void* d_out, int out_size) {
    (void)in_sizes; (void)n_in; (void)out_size;
    const float* x    = (const float*)d_in[0];
    const float* W1   = (const float*)d_in[1];
    const float* b1   = (const float*)d_in[2];
    const float* W2   = (const float*)d_in[3];
    const float* b2   = (const float*)d_in[4];
    const float* Wr2  = (const float*)d_in[5];
    const float* br2  = (const float*)d_in[6];
    // d_in[7..10]: W3, b3, Wr3, br3 — dead (layer 3 never reaches outputs)
    const float* W4   = (const float*)d_in[11];
    const float* b4   = (const float*)d_in[12];
    const float* Vth1 = (const float*)d_in[13];
    const float* tau1 = (const float*)d_in[14];
    const float* Vth2 = (const float*)d_in[15];
    const float* tau2 = (const float*)d_in[16];
    // d_in[17..18]: Vth3, tau3 — dead
    const float* tau_out = (const float*)d_in[19];
    float* out = (float*)d_out;

    k_transpose_x<<<dim3((T_STEPS + 31) / 32, CIN / 32, BATCH), dim3(32, 8)>>>(x);
    k_prep<<<512, 256>>>(W1, Wr2, W2);
    k_gemm_in1<<<dim3((T_STEPS * BATCH) / 128, NHID / 128), 256>>>(b1, br2);
    k_rsnn<<<NBLK, NT>>>(W4, b2, br2, b4, Vth1, tau1, Vth2, tau2, tau_out, out);
}

// round 8
// speedup vs baseline: 3.5109x; 1.0465x over previous
#include <cuda_runtime.h>
#include <cuda_bf16.h>
#include <cstdint>

#define T_STEPS 500
#define BATCH   512
#define CIN     128
#define NHID    512
#define NBLK    256          // independent blocks; 2 batch rows each (2 blocks/SM)
#define RPB     2
#define NT      256          // 128 threads per row; thread owns 4 neurons
#define ZROW    512          // sentinel row index (all zeros) for list padding

// ---------------- static device scratch (no allocations allowed) ----------------
__device__ float g_xtr[(size_t)T_STEPS * BATCH * CIN];    // [(t*B+b)][c]
__device__ float g_in1[(size_t)T_STEPS * BATCH * NHID];   // x@W1^T + b1 + br2
__device__ float g_W1T[CIN * NHID];                       // [c][n]
// combined gather table: per j (row of 1024 floats):
//   [q*4 .. q*4+3]        = Wr2[4q..4q+3][j]
//   [512 + q*4 .. +3]     = W2 [4q..4q+3][j]
// rows j = 512..515 stay zero (sentinel padding rows; .bss zero-init, never written)
__device__ float g_Wab[(size_t)(ZROW + 4) * 1024];

// ---------------- x[b][c][t] -> g_xtr[(t*B+b)][c] -------------------------------
__global__ void k_transpose_x(const float* __restrict__ x) {
    __shared__ float tile[32][33];
    int b = blockIdx.z;
    int t0 = blockIdx.x * 32, c0 = blockIdx.y * 32;
    int tx = threadIdx.x, ty = threadIdx.y;
#pragma unroll
    for (int i = 0; i < 32; i += 8) {
        int c = c0 + ty + i, t = t0 + tx;
        if (t < T_STEPS && c < CIN)
            tile[ty + i][tx] = x[((size_t)b * CIN + c) * T_STEPS + t];
    }
    __syncthreads();
#pragma unroll
    for (int i = 0; i < 32; i += 8) {
        int t = t0 + ty + i, c = c0 + tx;
        if (t < T_STEPS && c < CIN)
            g_xtr[((size_t)t * BATCH + b) * CIN + c] = tile[tx][ty + i];
    }
}

// ---------------- merged prep: W1 transpose + Wab pack ----------------------------
__global__ void k_prep(const float* __restrict__ W1,
                       const float* __restrict__ Wr2, const float* __restrict__ W2) {
    int blk = blockIdx.x;
    if (blk < 256) {
        int i = blk * 256 + threadIdx.x;       // 0 .. 512*128-1
        int j = i >> 7, q = i & 127, n0 = q * 4;
        float4 a, b;
        a.x = Wr2[(size_t)(n0 + 0) * NHID + j];
        a.y = Wr2[(size_t)(n0 + 1) * NHID + j];
        a.z = Wr2[(size_t)(n0 + 2) * NHID + j];
        a.w = Wr2[(size_t)(n0 + 3) * NHID + j];
        b.x = W2[(size_t)(n0 + 0) * NHID + j];
        b.y = W2[(size_t)(n0 + 1) * NHID + j];
        b.z = W2[(size_t)(n0 + 2) * NHID + j];
        b.w = W2[(size_t)(n0 + 3) * NHID + j];
        *(float4*)(g_Wab + (size_t)j * 1024 + q * 4) = a;
        *(float4*)(g_Wab + (size_t)j * 1024 + 512 + q * 4) = b;
    } else {
        int i = (blk - 256) * 256 + threadIdx.x;   // 0 .. CIN*NHID-1
        int c = i >> 9, n = i & 511;
        g_W1T[(size_t)c * NHID + n] = W1[(size_t)n * CIN + c];
    }
}

// ---------------- in1 = xtr @ W1T + (b1 + br2); 128x128 tile, 8x8/thread ---------
__global__ __launch_bounds__(256)
void k_gemm_in1(const float* __restrict__ b1, const float* __restrict__ br2) {
    __shared__ float As[16][132];   // [k][m]
    __shared__ float Bs[16][132];   // [k][n]
    const float* A = g_xtr;
    const float* B = g_W1T;
    int bm = blockIdx.x * 128, bn = blockIdx.y * 128;
    int tid = threadIdx.x;
    int tx = tid & 15, ty = tid >> 4;
    int arow = tid >> 1, acol = (tid & 1) * 8;   // A: one row-half per thread
    int brow = tid >> 4, bcol = (tid & 15) * 8;  // B: 16 rows x 128 cols

    float acc[8][8];
#pragma unroll
    for (int i = 0; i < 8; i++)
#pragma unroll
        for (int j = 0; j < 8; j++) acc[i][j] = 0.0f;

    for (int k0 = 0; k0 < CIN; k0 += 16) {
        float4 v0 = *(const float4*)(A + (size_t)(bm + arow) * CIN + k0 + acol);
        float4 v1 = *(const float4*)(A + (size_t)(bm + arow) * CIN + k0 + acol + 4);
        As[acol + 0][arow] = v0.x;
        As[acol + 1][arow] = v0.y;
        As[acol + 2][arow] = v0.z;
        As[acol + 3][arow] = v0.w;
        As[acol + 4][arow] = v1.x;
        As[acol + 5][arow] = v1.y;
        As[acol + 6][arow] = v1.z;
        As[acol + 7][arow] = v1.w;
        *(float4*)&Bs[brow][bcol] =
            *(const float4*)(B + (size_t)(k0 + brow) * NHID + bn + bcol);
        *(float4*)&Bs[brow][bcol + 4] =
            *(const float4*)(B + (size_t)(k0 + brow) * NHID + bn + bcol + 4);
        __syncthreads();
#pragma unroll
        for (int k = 0; k < 16; k++) {
            float4 av0 = *(const float4*)&As[k][ty * 8];
            float4 av1 = *(const float4*)&As[k][ty * 8 + 4];
            float4 bv0 = *(const float4*)&Bs[k][tx * 4];
            float4 bv1 = *(const float4*)&Bs[k][64 + tx * 4];
            float a[8] = {av0.x, av0.y, av0.z, av0.w, av1.x, av1.y, av1.z, av1.w};
            float b[8] = {bv0.x, bv0.y, bv0.z, bv0.w, bv1.x, bv1.y, bv1.z, bv1.w};
#pragma unroll
            for (int i = 0; i < 8; i++) {
#pragma unroll
                for (int j = 0; j < 8; j++) acc[i][j] += a[i] * b[j];
            }
        }
        __syncthreads();
    }
    int col0 = bn + tx * 4;
    int col1 = bn + 64 + tx * 4;
    float bb[8];
#pragma unroll
    for (int j = 0; j < 4; j++) {
        bb[j] = b1[col0 + j] + br2[col0 + j];
        bb[4 + j] = b1[col1 + j] + br2[col1 + j];
    }
#pragma unroll
    for (int i = 0; i < 8; i++) {
        size_t row = (size_t)(bm + ty * 8 + i);
        float4 o0, o1;
        o0.x = acc[i][0] + bb[0];
        o0.y = acc[i][1] + bb[1];
        o0.z = acc[i][2] + bb[2];
        o0.w = acc[i][3] + bb[3];
        o1.x = acc[i][4] + bb[4];
        o1.y = acc[i][5] + bb[5];
        o1.z = acc[i][6] + bb[6];
        o1.w = acc[i][7] + bb[7];
        *(float4*)(g_in1 + row * NHID + col0) = o0;
        *(float4*)(g_in1 + row * NHID + col1) = o1;
    }
}

// ---------------- chunked walks (lists padded to x4 with ZROW sentinels) ---------
__device__ __forceinline__ void walk_dual(const unsigned short* __restrict__ L, int c,
                                          const float* __restrict__ WAB, int q4,
                                          float4& a1, float4& f2) {
    for (int k = 0; k < c; k += 4) {
        ushort4 jj = *(const ushort4*)(L + k);
        const float* p0 = WAB + ((int)jj.x << 10) + q4;
        const float* p1 = WAB + ((int)jj.y << 10) + q4;
        const float* p2 = WAB + ((int)jj.z << 10) + q4;
        const float* p3 = WAB + ((int)jj.w << 10) + q4;
        float4 a0 = __ldg((const float4*)p0);
        float4 b0 = __ldg((const float4*)(p0 + 512));
        float4 a1r = __ldg((const float4*)p1);
        float4 b1r = __ldg((const float4*)(p1 + 512));
        float4 a2 = __ldg((const float4*)p2);
        float4 b2 = __ldg((const float4*)(p2 + 512));
        float4 a3 = __ldg((const float4*)p3);
        float4 b3 = __ldg((const float4*)(p3 + 512));
        a1.x += a0.x; a1.y += a0.y; a1.z += a0.z; a1.w += a0.w;
        f2.x += b0.x; f2.y += b0.y; f2.z += b0.z; f2.w += b0.w;
        a1.x += a1r.x; a1.y += a1r.y; a1.z += a1r.z; a1.w += a1r.w;
        f2.x += b1r.x; f2.y += b1r.y; f2.z += b1r.z; f2.w += b1r.w;
        a1.x += a2.x; a1.y += a2.y; a1.z += a2.z; a1.w += a2.w;
        f2.x += b2.x; f2.y += b2.y; f2.z += b2.z; f2.w += b2.w;
        a1.x += a3.x; a1.y += a3.y; a1.z += a3.z; a1.w += a3.w;
        f2.x += b3.x; f2.y += b3.y; f2.z += b3.z; f2.w += b3.w;
    }
}

__device__ __forceinline__ void walk_single(const unsigned short* __restrict__ L, int c,
                                            const float* __restrict__ WAB, int q4,
                                            float4& r2) {
    for (int k = 0; k < c; k += 4) {
        ushort4 jj = *(const ushort4*)(L + k);
        float4 a0 = __ldg((const float4*)(WAB + ((int)jj.x << 10) + q4));
        float4 a1r = __ldg((const float4*)(WAB + ((int)jj.y << 10) + q4));
        float4 a2 = __ldg((const float4*)(WAB + ((int)jj.z << 10) + q4));
        float4 a3 = __ldg((const float4*)(WAB + ((int)jj.w << 10) + q4));
        r2.x += a0.x; r2.y += a0.y; r2.z += a0.z; r2.w += a0.w;
        r2.x += a1r.x; r2.y += a1r.y; r2.z += a1r.z; r2.w += a1r.w;
        r2.x += a2.x; r2.y += a2.y; r2.z += a2.z; r2.w += a2.w;
        r2.x += a3.x; r2.y += a3.y; r2.z += a3.z; r2.w += a3.w;
    }
}

// ---------------- persistent per-block recurrent kernel (no grid sync) -----------
// 256 threads, 2 rows/block, 2 blocks per SM for dual independent streams.
__global__ __launch_bounds__(NT, 2)
void k_rsnn(const float* __restrict__ W4,
            const float* __restrict__ b2, const float* __restrict__ br2,
            const float* __restrict__ b4,
            const float* __restrict__ Vth1, const float* __restrict__ tau1,
            const float* __restrict__ Vth2, const float* __restrict__ tau2,
            const float* __restrict__ tau_out,
            float* __restrict__ out) {
    __shared__ float2 W4sh[NHID];
    __shared__ __align__(16) unsigned short slist1[2][RPB][4][128];
    __shared__ __align__(16) unsigned short slist2[2][RPB][4][128];
    __shared__ int scnt1[2][RPB][4];   // padded counts (multiple of 4)
    __shared__ int scnt2[2][RPB][4];
    __shared__ float redx[2][RPB][4];
    __shared__ float redy[2][RPB][4];

    const int tid = threadIdx.x;
    const int r = tid >> 7;                  // local row 0..1
    const int q = tid & 127;                 // neuron group 0..127
    const int n0 = q * 4;
    const int q4 = q * 4;
    const int lane = tid & 31;
    const int wq = q >> 5;                   // warp within row 0..3
    const int rowg = blockIdx.x * RPB + r;

    for (int i = tid; i < NHID; i += NT)
        W4sh[i] = make_float2(W4[i], W4[NHID + i]);
    if (tid < 2 * RPB * 4) {
        ((int*)scnt1)[tid] = 0;
        ((int*)scnt2)[tid] = 0;
    }
    __syncthreads();

    const float4 t1v = *(const float4*)(tau1 + n0);
    const float4 v1v = *(const float4*)(Vth1 + n0);
    const float4 t2v = *(const float4*)(tau2 + n0);
    const float4 v2v = *(const float4*)(Vth2 + n0);
    float4 bias2;
    bias2.x = b2[n0 + 0] + br2[n0 + 0];
    bias2.y = b2[n0 + 1] + br2[n0 + 1];
    bias2.z = b2[n0 + 2] + br2[n0 + 2];
    bias2.w = b2[n0 + 3] + br2[n0 + 3];

    const float4 z4 = make_float4(0.f, 0.f, 0.f, 0.f);
    float4 mem1 = z4, sp1 = z4, cnt1 = z4;
    float4 mem2 = z4, sp2 = z4, cnt2 = z4;
    unsigned nib2_prev = 0u;
    float memo_x = 0.f, memo_y = 0.f;
    const float to0 = tau_out[0], to1 = tau_out[1];
    const float b40 = b4[0], b41 = b4[1];

    const float* __restrict__ WAB = g_Wab;

    for (int p = 0; p <= T_STEPS + 1; p++) {
        const int rb1 = (p + 1) & 1;         // buf holding s1[p-1]
        const int rb2 = p & 1;               // buf holding s2[p-2]

        float4 i1v = z4;
        if (p < T_STEPS)
            i1v = __ldcg((const float4*)(g_in1 + ((size_t)p * BATCH + rowg) * NHID + n0));

        // ---- layer-2 recurrent walk FIRST (short; loads overlap the dual walk) ----
        float4 r2 = z4;
        const bool do_l2 = (p >= 1 && p <= T_STEPS);
        if (do_l2) {
#pragma unroll
            for (int w = 0; w < 4; w++)
                walk_single(slist2[rb2][r][w], scnt2[rb2][r][w], WAB, q4, r2);
        }

        // ---- combined walk over s1[p-1]: a1 (Wr2) and f2 (W2) ----
        float4 a1 = z4, f2 = z4;
        if (p <= T_STEPS) {
#pragma unroll
            for (int w = 0; w < 4; w++)
                walk_dual(slist1[rb1][r][w], scnt1[rb1][r][w], WAB, q4, a1, f2);
        }

        // ---- layer 1, t = p ----
        if (p < T_STEPS) {
            float4 i1 = i1v;
            i1.x += a1.x; i1.y += a1.y; i1.z += a1.z; i1.w += a1.w;
            mem1.x = t1v.x * mem1.x * (1.f - sp1.x) + i1.x;
            mem1.y = t1v.y * mem1.y * (1.f - sp1.y) + i1.y;
            mem1.z = t1v.z * mem1.z * (1.f - sp1.z) + i1.z;
            mem1.w = t1v.w * mem1.w * (1.f - sp1.w) + i1.w;
            float sx = (mem1.x > v1v.x) ? 1.f : 0.f;
            float sy = (mem1.y > v1v.y) ? 1.f : 0.f;
            float sz = (mem1.z > v1v.z) ? 1.f : 0.f;
            float sw = (mem1.w > v1v.w) ? 1.f : 0.f;
            sp1 = make_float4(sx, sy, sz, sw);
            cnt1.x += sx; cnt1.y += sy; cnt1.z += sz; cnt1.w += sw;
            unsigned nib = (sx > 0.f ? 1u : 0u) | (sy > 0.f ? 2u : 0u) |
                           (sz > 0.f ? 4u : 0u) | (sw > 0.f ? 8u : 0u);
            int cme = __popc(nib);
            int scan = cme;
#pragma unroll
            for (int d = 1; d < 32; d <<= 1) {
                int v = __shfl_up_sync(0xffffffffu, scan, d);
                if (lane >= d) scan += v;
            }
            int base = scan - cme;
            unsigned m = nib;
            unsigned short* Lw = slist1[p & 1][r][wq];
            while (m) {
                int b = __ffs(m) - 1;
                m &= m - 1u;
                Lw[base++] = (unsigned short)(n0 + b);
            }
            int ctot = __shfl_sync(0xffffffffu, scan, 31);
            int cpad = (ctot + 3) & ~3;
            if (lane < cpad - ctot) Lw[ctot + lane] = (unsigned short)ZROW;
            if (lane == 31) scnt1[p & 1][r][wq] = cpad;
        }

        // ---- layer 2, t = p-1 ----
        unsigned nib2_new = 0u;
        if (do_l2) {
            float4 i2;
            i2.x = f2.x + r2.x + bias2.x;
            i2.y = f2.y + r2.y + bias2.y;
            i2.z = f2.z + r2.z + bias2.z;
            i2.w = f2.w + r2.w + bias2.w;
            mem2.x = t2v.x * mem2.x * (1.f - sp2.x) + i2.x;
            mem2.y = t2v.y * mem2.y * (1.f - sp2.y) + i2.y;
            mem2.z = t2v.z * mem2.z * (1.f - sp2.z) + i2.z;
            mem2.w = t2v.w * mem2.w * (1.f - sp2.w) + i2.w;
            float sx = (mem2.x > v2v.x) ? 1.f : 0.f;
            float sy = (mem2.y > v2v.y) ? 1.f : 0.f;
            float sz = (mem2.z > v2v.z) ? 1.f : 0.f;
            float sw = (mem2.w > v2v.w) ? 1.f : 0.f;
            sp2 = make_float4(sx, sy, sz, sw);
            cnt2.x += sx; cnt2.y += sy; cnt2.z += sz; cnt2.w += sw;
            nib2_new = (sx > 0.f ? 1u : 0u) | (sy > 0.f ? 2u : 0u) |
                       (sz > 0.f ? 4u : 0u) | (sw > 0.f ? 8u : 0u);
            int cme = __popc(nib2_new);
            int scan = cme;
#pragma unroll
            for (int d = 1; d < 32; d <<= 1) {
                int v = __shfl_up_sync(0xffffffffu, scan, d);
                if (lane >= d) scan += v;
            }
            int base = scan - cme;
            unsigned m = nib2_new;
            unsigned short* Lw = slist2[(p + 1) & 1][r][wq];
            while (m) {
                int b = __ffs(m) - 1;
                m &= m - 1u;
                Lw[base++] = (unsigned short)(n0 + b);
            }
            int ctot = __shfl_sync(0xffffffffu, scan, 31);
            int cpad = (ctot + 3) & ~3;
            if (lane < cpad - ctot) Lw[ctot + lane] = (unsigned short)ZROW;
            if (lane == 31) scnt2[(p + 1) & 1][r][wq] = cpad;
        }

        // ---- readout partials for t = p-2 (uses nib2_prev = s2[p-2]) ----
        {
            float ax = 0.f, ay = 0.f;
            unsigned nb = nib2_prev;
            if (nb & 1u) { float2 t = W4sh[n0 + 0]; ax += t.x; ay += t.y; }
            if (nb & 2u) { float2 t = W4sh[n0 + 1]; ax += t.x; ay += t.y; }
            if (nb & 4u) { float2 t = W4sh[n0 + 2]; ax += t.x; ay += t.y; }
            if (nb & 8u) { float2 t = W4sh[n0 + 3]; ax += t.x; ay += t.y; }
#pragma unroll
            for (int off = 16; off > 0; off >>= 1) {
                ax += __shfl_down_sync(0xffffffffu, ax, off);
                ay += __shfl_down_sync(0xffffffffu, ay, off);
            }
            if (lane == 0) {
                redx[p & 1][r][wq] = ax;
                redy[p & 1][r][wq] = ay;
            }
        }
        nib2_prev = nib2_new;

        __syncthreads();   // the ONLY sync per phase

        // ---- finalize readout t = p-2 ----
        if (p >= 2 && q == 0) {
            int par = p & 1;
            float ax = ((redx[par][r][0] + redx[par][r][1]) +
                        (redx[par][r][2] + redx[par][r][3]));
            float ay = ((redy[par][r][0] + redy[par][r][1]) +
                        (redy[par][r][2] + redy[par][r][3]));
            memo_x = to0 * memo_x + ax + b40;
            memo_y = to1 * memo_y + ay + b41;
            int t = p - 2;
            out[(size_t)rowg * (2 * T_STEPS) + t] = memo_x;
            out[(size_t)rowg * (2 * T_STEPS) + T_STEPS + t] = memo_y;
        }
    }

    // ---- spike-count outputs ----
    const float inv = 1.f / (float)T_STEPS;
    float* sc1 = out + (size_t)BATCH * 2 * T_STEPS;
    float* sc2 = sc1 + (size_t)BATCH * NHID;
    *(float4*)(sc1 + (size_t)rowg * NHID + n0) =
        make_float4(cnt1.x * inv, cnt1.y * inv, cnt1.z * inv, cnt1.w * inv);
    *(float4*)(sc2 + (size_t)rowg * NHID + n0) =
        make_float4(cnt2.x * inv, cnt2.y * inv, cnt2.z * inv, cnt2.w * inv);
}

// ---------------- launch ----------------------------------------------------------
extern "C" void kernel_launch(void* const* d_in, const int* in_sizes, int n_in,
                              void* d_out, int out_size) {
    (void)in_sizes; (void)n_in; (void)out_size;
    const float* x    = (const float*)d_in[0];
    const float* W1   = (const float*)d_in[1];
    const float* b1   = (const float*)d_in[2];
    const float* W2   = (const float*)d_in[3];
    const float* b2   = (const float*)d_in[4];
    const float* Wr2  = (const float*)d_in[5];
    const float* br2  = (const float*)d_in[6];
    // d_in[7..10]: W3, b3, Wr3, br3 — dead (layer 3 never reaches outputs)
    const float* W4   = (const float*)d_in[11];
    const float* b4   = (const float*)d_in[12];
    const float* Vth1 = (const float*)d_in[13];
    const float* tau1 = (const float*)d_in[14];
    const float* Vth2 = (const float*)d_in[15];
    const float* tau2 = (const float*)d_in[16];
    // d_in[17..18]: Vth3, tau3 — dead
    const float* tau_out = (const float*)d_in[19];
    float* out = (float*)d_out;

    k_transpose_x<<<dim3((T_STEPS + 31) / 32, CIN / 32, BATCH), dim3(32, 8)>>>(x);
    k_prep<<<512, 256>>>(W1, Wr2, W2);
    k_gemm_in1<<<dim3((T_STEPS * BATCH) / 128, NHID / 128), 256>>>(b1, br2);
    k_rsnn<<<NBLK, NT>>>(W4, b2, br2, b4, Vth1, tau1, Vth2, tau2, tau_out, out);
}

// round 9
// speedup vs baseline: 3.5282x; 1.0049x over previous
#include <cuda_runtime.h>
#include <cuda_bf16.h>
#include <cstdint>

#define T_STEPS 500
#define BATCH   512
#define CIN     128
#define NHID    512
#define NBLK    512          // independent blocks; 1 batch row each (4 blocks/SM)
#define NT      128          // 128 threads per row; thread owns 4 neurons
#define ZROW    512          // sentinel row index (all zeros) for list padding

// ---------------- static device scratch (no allocations allowed) ----------------
__device__ float g_xtr[(size_t)T_STEPS * BATCH * CIN];    // [(t*B+b)][c]
__device__ float g_in1[(size_t)T_STEPS * BATCH * NHID];   // x@W1^T + b1 + br2
__device__ float g_W1T[CIN * NHID];                       // [c][n]
// combined gather table: per j (row of 1024 floats):
//   [q*4 .. q*4+3]    = Wr2[4q..4q+3][j]
//   [512 + q*4 .. +3] = W2 [4q..4q+3][j]
// rows j = 512..515 stay zero (sentinel padding rows; .bss zero-init, never written)
__device__ float g_Wab[(size_t)(ZROW + 4) * 1024];

// ---------------- x[b][c][t] -> g_xtr[(t*B+b)][c] -------------------------------
__global__ void k_transpose_x(const float* __restrict__ x) {
    __shared__ float tile[32][33];
    int b = blockIdx.z;
    int t0 = blockIdx.x * 32, c0 = blockIdx.y * 32;
    int tx = threadIdx.x, ty = threadIdx.y;
#pragma unroll
    for (int i = 0; i < 32; i += 8) {
        int c = c0 + ty + i, t = t0 + tx;
        if (t < T_STEPS && c < CIN)
            tile[ty + i][tx] = x[((size_t)b * CIN + c) * T_STEPS + t];
    }
    __syncthreads();
#pragma unroll
    for (int i = 0; i < 32; i += 8) {
        int t = t0 + ty + i, c = c0 + tx;
        if (t < T_STEPS && c < CIN)
            g_xtr[((size_t)t * BATCH + b) * CIN + c] = tile[tx][ty + i];
    }
}

// ---------------- merged prep: W1 transpose + Wab pack ----------------------------
__global__ void k_prep(const float* __restrict__ W1,
                       const float* __restrict__ Wr2, const float* __restrict__ W2) {
    int blk = blockIdx.x;
    if (blk < 256) {
        int i = blk * 256 + threadIdx.x;       // 0 .. 512*128-1
        int j = i >> 7, q = i & 127, n0 = q * 4;
        float4 a, b;
        a.x = Wr2[(size_t)(n0 + 0) * NHID + j];
        a.y = Wr2[(size_t)(n0 + 1) * NHID + j];
        a.z = Wr2[(size_t)(n0 + 2) * NHID + j];
        a.w = Wr2[(size_t)(n0 + 3) * NHID + j];
        b.x = W2[(size_t)(n0 + 0) * NHID + j];
        b.y = W2[(size_t)(n0 + 1) * NHID + j];
        b.z = W2[(size_t)(n0 + 2) * NHID + j];
        b.w = W2[(size_t)(n0 + 3) * NHID + j];
        *(float4*)(g_Wab + (size_t)j * 1024 + q * 4) = a;
        *(float4*)(g_Wab + (size_t)j * 1024 + 512 + q * 4) = b;
    } else {
        int i = (blk - 256) * 256 + threadIdx.x;   // 0 .. CIN*NHID-1
        int c = i >> 9, n = i & 511;
        g_W1T[(size_t)c * NHID + n] = W1[(size_t)n * CIN + c];
    }
}

// ---------------- in1 = xtr @ W1T + (b1 + br2); 128x128 tile, 8x8/thread ---------
__global__ __launch_bounds__(256)
void k_gemm_in1(const float* __restrict__ b1, const float* __restrict__ br2) {
    __shared__ float As[16][132];   // [k][m]
    __shared__ float Bs[16][132];   // [k][n]
    const float* A = g_xtr;
    const float* B = g_W1T;
    int bm = blockIdx.x * 128, bn = blockIdx.y * 128;
    int tid = threadIdx.x;
    int tx = tid & 15, ty = tid >> 4;
    int arow = tid >> 1, acol = (tid & 1) * 8;
    int brow = tid >> 4, bcol = (tid & 15) * 8;

    float acc[8][8];
#pragma unroll
    for (int i = 0; i < 8; i++)
#pragma unroll
        for (int j = 0; j < 8; j++) acc[i][j] = 0.0f;

    for (int k0 = 0; k0 < CIN; k0 += 16) {
        float4 v0 = *(const float4*)(A + (size_t)(bm + arow) * CIN + k0 + acol);
        float4 v1 = *(const float4*)(A + (size_t)(bm + arow) * CIN + k0 + acol + 4);
        As[acol + 0][arow] = v0.x;
        As[acol + 1][arow] = v0.y;
        As[acol + 2][arow] = v0.z;
        As[acol + 3][arow] = v0.w;
        As[acol + 4][arow] = v1.x;
        As[acol + 5][arow] = v1.y;
        As[acol + 6][arow] = v1.z;
        As[acol + 7][arow] = v1.w;
        *(float4*)&Bs[brow][bcol] =
            *(const float4*)(B + (size_t)(k0 + brow) * NHID + bn + bcol);
        *(float4*)&Bs[brow][bcol + 4] =
            *(const float4*)(B + (size_t)(k0 + brow) * NHID + bn + bcol + 4);
        __syncthreads();
#pragma unroll
        for (int k = 0; k < 16; k++) {
            float4 av0 = *(const float4*)&As[k][ty * 8];
            float4 av1 = *(const float4*)&As[k][ty * 8 + 4];
            float4 bv0 = *(const float4*)&Bs[k][tx * 4];
            float4 bv1 = *(const float4*)&Bs[k][64 + tx * 4];
            float a[8] = {av0.x, av0.y, av0.z, av0.w, av1.x, av1.y, av1.z, av1.w};
            float b[8] = {bv0.x, bv0.y, bv0.z, bv0.w, bv1.x, bv1.y, bv1.z, bv1.w};
#pragma unroll
            for (int i = 0; i < 8; i++) {
#pragma unroll
                for (int j = 0; j < 8; j++) acc[i][j] += a[i] * b[j];
            }
        }
        __syncthreads();
    }
    int col0 = bn + tx * 4;
    int col1 = bn + 64 + tx * 4;
    float bb[8];
#pragma unroll
    for (int j = 0; j < 4; j++) {
        bb[j] = b1[col0 + j] + br2[col0 + j];
        bb[4 + j] = b1[col1 + j] + br2[col1 + j];
    }
#pragma unroll
    for (int i = 0; i < 8; i++) {
        size_t row = (size_t)(bm + ty * 8 + i);
        float4 o0, o1;
        o0.x = acc[i][0] + bb[0];
        o0.y = acc[i][1] + bb[1];
        o0.z = acc[i][2] + bb[2];
        o0.w = acc[i][3] + bb[3];
        o1.x = acc[i][4] + bb[4];
        o1.y = acc[i][5] + bb[5];
        o1.z = acc[i][6] + bb[6];
        o1.w = acc[i][7] + bb[7];
        *(float4*)(g_in1 + row * NHID + col0) = o0;
        *(float4*)(g_in1 + row * NHID + col1) = o1;
    }
}

// ---------------- walks: explicit next-chunk prefetch, ascending j order ---------
__device__ __forceinline__ void acc_add(float4& a, const float4& v) {
    a.x += v.x; a.y += v.y; a.z += v.z; a.w += v.w;
}

// dual walk with software double-buffering: chunk k+1's loads issue before
// chunk k's accumulation retires. Accumulation order identical to simple loop.
__device__ __forceinline__ void walk_dual(const unsigned short* __restrict__ L, int c,
                                          const float* __restrict__ WAB, int q4,
                                          float4& a1, float4& f2) {
    if (c <= 0) return;
    ushort4 jj = *(const ushort4*)(L);
    const float* p0 = WAB + ((int)jj.x << 10) + q4;
    const float* p1 = WAB + ((int)jj.y << 10) + q4;
    const float* p2 = WAB + ((int)jj.z << 10) + q4;
    const float* p3 = WAB + ((int)jj.w << 10) + q4;
    float4 a0 = __ldg((const float4*)p0), b0 = __ldg((const float4*)(p0 + 512));
    float4 c1 = __ldg((const float4*)p1), d1 = __ldg((const float4*)(p1 + 512));
    float4 a2 = __ldg((const float4*)p2), b2 = __ldg((const float4*)(p2 + 512));
    float4 a3 = __ldg((const float4*)p3), b3 = __ldg((const float4*)(p3 + 512));
    for (int k = 4; k < c; k += 4) {
        ushort4 jn = *(const ushort4*)(L + k);
        const float* n0p = WAB + ((int)jn.x << 10) + q4;
        const float* n1p = WAB + ((int)jn.y << 10) + q4;
        const float* n2p = WAB + ((int)jn.z << 10) + q4;
        const float* n3p = WAB + ((int)jn.w << 10) + q4;
        float4 na0 = __ldg((const float4*)n0p), nb0 = __ldg((const float4*)(n0p + 512));
        float4 nc1 = __ldg((const float4*)n1p), nd1 = __ldg((const float4*)(n1p + 512));
        float4 na2 = __ldg((const float4*)n2p), nb2 = __ldg((const float4*)(n2p + 512));
        float4 na3 = __ldg((const float4*)n3p), nb3 = __ldg((const float4*)(n3p + 512));
        acc_add(a1, a0); acc_add(f2, b0);
        acc_add(a1, c1); acc_add(f2, d1);
        acc_add(a1, a2); acc_add(f2, b2);
        acc_add(a1, a3); acc_add(f2, b3);
        a0 = na0; b0 = nb0; c1 = nc1; d1 = nd1;
        a2 = na2; b2 = nb2; a3 = na3; b3 = nb3;
    }
    acc_add(a1, a0); acc_add(f2, b0);
    acc_add(a1, c1); acc_add(f2, d1);
    acc_add(a1, a2); acc_add(f2, b2);
    acc_add(a1, a3); acc_add(f2, b3);
}

__device__ __forceinline__ void walk_single(const unsigned short* __restrict__ L, int c,
                                            const float* __restrict__ WAB, int q4,
                                            float4& r2) {
    for (int k = 0; k < c; k += 4) {
        ushort4 jj = *(const ushort4*)(L + k);
        float4 a0 = __ldg((const float4*)(WAB + ((int)jj.x << 10) + q4));
        float4 a1r = __ldg((const float4*)(WAB + ((int)jj.y << 10) + q4));
        float4 a2 = __ldg((const float4*)(WAB + ((int)jj.z << 10) + q4));
        float4 a3 = __ldg((const float4*)(WAB + ((int)jj.w << 10) + q4));
        acc_add(r2, a0); acc_add(r2, a1r); acc_add(r2, a2); acc_add(r2, a3);
    }
}

// ballot-based ordered compaction (lane-major, bit-minor = ascending j).
// Returns padded count; every lane gets the same value.
__device__ __forceinline__ int compact_list(unsigned nib, int lane, int n0,
                                            unsigned short* __restrict__ Lw) {
    unsigned B0 = __ballot_sync(0xffffffffu, nib & 1u);
    unsigned B1 = __ballot_sync(0xffffffffu, nib & 2u);
    unsigned B2 = __ballot_sync(0xffffffffu, nib & 4u);
    unsigned B3 = __ballot_sync(0xffffffffu, nib & 8u);
    unsigned lt = (1u << lane) - 1u;
    int base = __popc(B0 & lt) + __popc(B1 & lt) + __popc(B2 & lt) + __popc(B3 & lt);
    int ctot = __popc(B0) + __popc(B1) + __popc(B2) + __popc(B3);
    unsigned m = nib;
    while (m) {
        int b = __ffs(m) - 1;
        m &= m - 1u;
        Lw[base++] = (unsigned short)(n0 + b);
    }
    int cpad = (ctot + 3) & ~3;
    if (lane < cpad - ctot) Lw[ctot + lane] = (unsigned short)ZROW;
    return cpad;
}

// ---------------- persistent per-block recurrent kernel (no grid sync) -----------
// 128 threads, 1 row/block, 4 blocks per SM for four independent streams.
__global__ __launch_bounds__(NT, 4)
void k_rsnn(const float* __restrict__ W4,
            const float* __restrict__ b2, const float* __restrict__ br2,
            const float* __restrict__ b4,
            const float* __restrict__ Vth1, const float* __restrict__ tau1,
            const float* __restrict__ Vth2, const float* __restrict__ tau2,
            const float* __restrict__ tau_out,
            float* __restrict__ out) {
    __shared__ float2 W4sh[NHID];
    __shared__ __align__(16) unsigned short slist1[2][4][128];
    __shared__ __align__(16) unsigned short slist2[2][4][128];
    __shared__ int scnt1[2][4];   // padded counts (multiple of 4)
    __shared__ int scnt2[2][4];
    __shared__ float redx[2][4];
    __shared__ float redy[2][4];

    const int tid = threadIdx.x;             // == q, neuron group 0..127
    const int q = tid;
    const int n0 = q * 4;
    const int q4 = q * 4;
    const int lane = tid & 31;
    const int wq = tid >> 5;                  // warp 0..3
    const int rowg = blockIdx.x;              // global batch row

    for (int i = tid; i < NHID; i += NT)
        W4sh[i] = make_float2(W4[i], W4[NHID + i]);
    if (tid < 2 * 4) {
        ((int*)scnt1)[tid] = 0;
        ((int*)scnt2)[tid] = 0;
    }
    __syncthreads();

    const float4 t1v = *(const float4*)(tau1 + n0);
    const float4 v1v = *(const float4*)(Vth1 + n0);
    const float4 t2v = *(const float4*)(tau2 + n0);
    const float4 v2v = *(const float4*)(Vth2 + n0);
    float4 bias2;
    bias2.x = b2[n0 + 0] + br2[n0 + 0];
    bias2.y = b2[n0 + 1] + br2[n0 + 1];
    bias2.z = b2[n0 + 2] + br2[n0 + 2];
    bias2.w = b2[n0 + 3] + br2[n0 + 3];

    const float4 z4 = make_float4(0.f, 0.f, 0.f, 0.f);
    float4 mem1 = z4, sp1 = z4, cnt1 = z4;
    float4 mem2 = z4, sp2 = z4, cnt2 = z4;
    unsigned nib2_prev = 0u;
    float memo_x = 0.f, memo_y = 0.f;
    const float to0 = tau_out[0], to1 = tau_out[1];
    const float b40 = b4[0], b41 = b4[1];

    const float* __restrict__ WAB = g_Wab;

    for (int p = 0; p <= T_STEPS + 1; p++) {
        const int rb1 = (p + 1) & 1;          // buf holding s1[p-1]
        const int rb2 = p & 1;                // buf holding s2[p-2]

        float4 i1v = z4;
        if (p < T_STEPS)
            i1v = __ldcg((const float4*)(g_in1 + ((size_t)p * BATCH + rowg) * NHID + n0));

        // ---- layer-2 recurrent walk first (short; overlaps the dual walk) ----
        float4 r2 = z4;
        const bool do_l2 = (p >= 1 && p <= T_STEPS);
        if (do_l2) {
#pragma unroll
            for (int w = 0; w < 4; w++)
                walk_single(slist2[rb2][w], scnt2[rb2][w], WAB, q4, r2);
        }

        // ---- combined walk over s1[p-1]: a1 (Wr2) and f2 (W2) ----
        float4 a1 = z4, f2 = z4;
        if (p <= T_STEPS) {
#pragma unroll
            for (int w = 0; w < 4; w++)
                walk_dual(slist1[rb1][w], scnt1[rb1][w], WAB, q4, a1, f2);
        }

        // ---- layer 1, t = p ----
        if (p < T_STEPS) {
            float4 i1 = i1v;
            i1.x += a1.x; i1.y += a1.y; i1.z += a1.z; i1.w += a1.w;
            mem1.x = t1v.x * mem1.x * (1.f - sp1.x) + i1.x;
            mem1.y = t1v.y * mem1.y * (1.f - sp1.y) + i1.y;
            mem1.z = t1v.z * mem1.z * (1.f - sp1.z) + i1.z;
            mem1.w = t1v.w * mem1.w * (1.f - sp1.w) + i1.w;
            float sx = (mem1.x > v1v.x) ? 1.f : 0.f;
            float sy = (mem1.y > v1v.y) ? 1.f : 0.f;
            float sz = (mem1.z > v1v.z) ? 1.f : 0.f;
            float sw = (mem1.w > v1v.w) ? 1.f : 0.f;
            sp1 = make_float4(sx, sy, sz, sw);
            cnt1.x += sx; cnt1.y += sy; cnt1.z += sz; cnt1.w += sw;
            unsigned nib = (sx > 0.f ? 1u : 0u) | (sy > 0.f ? 2u : 0u) |
                           (sz > 0.f ? 4u : 0u) | (sw > 0.f ? 8u : 0u);
            int cpad = compact_list(nib, lane, n0, slist1[p & 1][wq]);
            if (lane == 0) scnt1[p & 1][wq] = cpad;
        }

        // ---- layer 2, t = p-1 ----
        unsigned nib2_new = 0u;
        if (do_l2) {
            float4 i2;
            i2.x = f2.x + r2.x + bias2.x;
            i2.y = f2.y + r2.y + bias2.y;
            i2.z = f2.z + r2.z + bias2.z;
            i2.w = f2.w + r2.w + bias2.w;
            mem2.x = t2v.x * mem2.x * (1.f - sp2.x) + i2.x;
            mem2.y = t2v.y * mem2.y * (1.f - sp2.y) + i2.y;
            mem2.z = t2v.z * mem2.z * (1.f - sp2.z) + i2.z;
            mem2.w = t2v.w * mem2.w * (1.f - sp2.w) + i2.w;
            float sx = (mem2.x > v2v.x) ? 1.f : 0.f;
            float sy = (mem2.y > v2v.y) ? 1.f : 0.f;
            float sz = (mem2.z > v2v.z) ? 1.f : 0.f;
            float sw = (mem2.w > v2v.w) ? 1.f : 0.f;
            sp2 = make_float4(sx, sy, sz, sw);
            cnt2.x += sx; cnt2.y += sy; cnt2.z += sz; cnt2.w += sw;
            nib2_new = (sx > 0.f ? 1u : 0u) | (sy > 0.f ? 2u : 0u) |
                       (sz > 0.f ? 4u : 0u) | (sw > 0.f ? 8u : 0u);
            int cpad = compact_list(nib2_new, lane, n0, slist2[(p + 1) & 1][wq]);
            if (lane == 0) scnt2[(p + 1) & 1][wq] = cpad;
        }

        // ---- readout partials for t = p-2 (uses nib2_prev = s2[p-2]) ----
        {
            float ax = 0.f, ay = 0.f;
            unsigned nb = nib2_prev;
            if (nb & 1u) { float2 t = W4sh[n0 + 0]; ax += t.x; ay += t.y; }
            if (nb & 2u) { float2 t = W4sh[n0 + 1]; ax += t.x; ay += t.y; }
            if (nb & 4u) { float2 t = W4sh[n0 + 2]; ax += t.x; ay += t.y; }
            if (nb & 8u) { float2 t = W4sh[n0 + 3]; ax += t.x; ay += t.y; }
#pragma unroll
            for (int off = 16; off > 0; off >>= 1) {
                ax += __shfl_down_sync(0xffffffffu, ax, off);
                ay += __shfl_down_sync(0xffffffffu, ay, off);
            }
            if (lane == 0) {
                redx[p & 1][wq] = ax;
                redy[p & 1][wq] = ay;
            }
        }
        nib2_prev = nib2_new;

        __syncthreads();   // the ONLY sync per phase (4 warps)

        // ---- finalize readout t = p-2 ----
        if (p >= 2 && tid == 0) {
            int par = p & 1;
            float ax = ((redx[par][0] + redx[par][1]) + (redx[par][2] + redx[par][3]));
            float ay = ((redy[par][0] + redy[par][1]) + (redy[par][2] + redy[par][3]));
            memo_x = to0 * memo_x + ax + b40;
            memo_y = to1 * memo_y + ay + b41;
            int t = p - 2;
            out[(size_t)rowg * (2 * T_STEPS) + t] = memo_x;
            out[(size_t)rowg * (2 * T_STEPS) + T_STEPS + t] = memo_y;
        }
    }

    // ---- spike-count outputs ----
    const float inv = 1.f / (float)T_STEPS;
    float* sc1 = out + (size_t)BATCH * 2 * T_STEPS;
    float* sc2 = sc1 + (size_t)BATCH * NHID;
    *(float4*)(sc1 + (size_t)rowg * NHID + n0) =
        make_float4(cnt1.x * inv, cnt1.y * inv, cnt1.z * inv, cnt1.w * inv);
    *(float4*)(sc2 + (size_t)rowg * NHID + n0) =
        make_float4(cnt2.x * inv, cnt2.y * inv, cnt2.z * inv, cnt2.w * inv);
}

// ---------------- launch ----------------------------------------------------------
extern "C" void kernel_launch(void* const* d_in, const int* in_sizes, int n_in,
                              void* d_out, int out_size) {
    (void)in_sizes; (void)n_in; (void)out_size;
    const float* x    = (const float*)d_in[0];
    const float* W1   = (const float*)d_in[1];
    const float* b1   = (const float*)d_in[2];
    const float* W2   = (const float*)d_in[3];
    const float* b2   = (const float*)d_in[4];
    const float* Wr2  = (const float*)d_in[5];
    const float* br2  = (const float*)d_in[6];
    // d_in[7..10]: W3, b3, Wr3, br3 — dead (layer 3 never reaches outputs)
    const float* W4   = (const float*)d_in[11];
    const float* b4   = (const float*)d_in[12];
    const float* Vth1 = (const float*)d_in[13];
    const float* tau1 = (const float*)d_in[14];
    const float* Vth2 = (const float*)d_in[15];
    const float* tau2 = (const float*)d_in[16];
    // d_in[17..18]: Vth3, tau3 — dead
    const float* tau_out = (const float*)d_in[19];
    float* out = (float*)d_out;

    k_transpose_x<<<dim3((T_STEPS + 31) / 32, CIN / 32, BATCH), dim3(32, 8)>>>(x);
    k_prep<<<512, 256>>>(W1, Wr2, W2);
    k_gemm_in1<<<dim3((T_STEPS * BATCH) / 128, NHID / 128), 256>>>(b1, br2);
    k_rsnn<<<NBLK, NT>>>(W4, b2, br2, b4, Vth1, tau1, Vth2, tau2, tau_out, out);
}